// round 7
// baseline (speedup 1.0000x reference)
#include <cuda_runtime.h>
#include <cstdint>
#include <math.h>

constexpr int SEQ = 2048, DIM = 2048, NH = 16, NKV = 4, HD = 128, FF = 8192;
constexpr float EPSV = 1e-6f;

// ---------------------------------------------------------------------------
// Scratch (device globals — allocation forbidden)
// ---------------------------------------------------------------------------
__device__ float g_h1[SEQ * DIM];
__device__ float g_q [SEQ * NH * HD];
__device__ float g_k [SEQ * NKV * HD];
__device__ float g_v [SEQ * NKV * HD];
__device__ float g_sc[(long)NH * SEQ * SEQ];
__device__ float g_at[SEQ * NH * HD];
__device__ float g_x2[SEQ * DIM];
__device__ float g_h2[SEQ * DIM];
__device__ float g_gg[(long)SEQ * FF];
__device__ float g_mm[(long)SEQ * FF];
__device__ double g_invf[64];
__device__ float2 g_cs[SEQ * 64];

// ---------------------------------------------------------------------------
__device__ __forceinline__ uint32_t smem_u32(const void* p) {
    uint32_t a;
    asm("{ .reg .u64 t; cvta.to.shared.u64 t, %1; cvt.u32.u64 %0, t; }" : "=r"(a) : "l"(p));
    return a;
}
__device__ __forceinline__ float to_tf32(float x) {
    uint32_t u;
    asm("cvt.rna.tf32.f32 %0, %1;" : "=r"(u) : "f"(x));
    return __uint_as_float(u);
}
__device__ __forceinline__ uint32_t to_tf32_u(float x) {
    uint32_t u;
    asm("cvt.rna.tf32.f32 %0, %1;" : "=r"(u) : "f"(x));
    return u;
}
__device__ __forceinline__ void cp16(uint32_t dst, const void* src) {
    asm volatile("cp.async.cg.shared.global [%0], [%1], 16;" :: "r"(dst), "l"(src) : "memory");
}
__device__ __forceinline__ void cp_commit() {
    asm volatile("cp.async.commit_group;" ::: "memory");
}
template<int N> __device__ __forceinline__ void cp_wait() {
    asm volatile("cp.async.wait_group %0;" :: "n"(N) : "memory");
}
__device__ __forceinline__ void mma_tf32(float* c, const uint32_t* a, const uint32_t* b) {
    asm volatile(
        "mma.sync.aligned.m16n8k8.row.col.f32.tf32.tf32.f32 "
        "{%0,%1,%2,%3}, {%4,%5,%6,%7}, {%8,%9}, {%0,%1,%2,%3};"
        : "+f"(c[0]), "+f"(c[1]), "+f"(c[2]), "+f"(c[3])
        : "r"(a[0]), "r"(a[1]), "r"(a[2]), "r"(a[3]), "r"(b[0]), "r"(b[1]));
}
__device__ __forceinline__ void ldsm_x4(uint32_t* r, uint32_t addr) {
    asm volatile("ldmatrix.sync.aligned.m8n8.x4.shared.b16 {%0,%1,%2,%3}, [%4];"
                 : "=r"(r[0]), "=r"(r[1]), "=r"(r[2]), "=r"(r[3]) : "r"(addr));
}

__device__ __forceinline__ float fexp(float x) {  // accurate for x <= 0
    float t = x * 1.4426950408889634f;
    float r = rintf(t), f = t - r;
    int i = (int)r;
    float p = 0.0013333558f;
    p = fmaf(p, f, 0.0096181291f);
    p = fmaf(p, f, 0.0555041087f);
    p = fmaf(p, f, 0.2402264476f);
    p = fmaf(p, f, 0.6931471806f);
    p = fmaf(p, f, 1.0f);
    float s = __int_as_float((i + 127) << 23);
    return (x < -80.f) ? 0.f : p * s;
}
__device__ __forceinline__ float silu(float g) {
    float t = fexp(-fabsf(g));
    float s = (g >= 0.f) ? 1.f / (1.f + t) : t / (1.f + t);
    return g * s;
}

// ---------------- rmsnorm (tf32-rounded out) -------------------------------
__global__ __launch_bounds__(256)
void rmsnorm_kernel(const float* __restrict__ x, const float* __restrict__ w,
                    float* __restrict__ o) {
    const int row = blockIdx.x;
    const float* xr = x + (size_t)row * DIM;
    float s = 0.f;
    for (int j = threadIdx.x; j < DIM; j += 256) { float v = xr[j]; s += v * v; }
    __shared__ float red[256];
    red[threadIdx.x] = s;
    __syncthreads();
    for (int st = 128; st > 0; st >>= 1) {
        if (threadIdx.x < st) red[threadIdx.x] += red[threadIdx.x + st];
        __syncthreads();
    }
    const float inv = rsqrtf(red[0] * (1.0f / DIM) + EPSV);
    float* orow = o + (size_t)row * DIM;
    for (int j = threadIdx.x; j < DIM; j += 256)
        orow[j] = to_tf32(xr[j] * inv * w[j]);
}

// ---------------- RoPE -----------------------------------------------------
__global__ void init_invf_kernel() { g_invf[threadIdx.x] = pow(10000.0, -(double)threadIdx.x / 64.0); }
__global__ void rope_table_kernel() {
    int s = blockIdx.x, d = threadIdx.x;
    double ang = (double)s * g_invf[d];
    const double twopi = 6.283185307179586476925287;
    double r = ang - twopi * floor(ang / twopi + 0.5);
    float rf = (float)r;
    g_cs[s * 64 + d] = make_float2(cosf(rf), sinf(rf));
}
__global__ void rope_apply_kernel(float* __restrict__ q, float* __restrict__ k) {
    const int s = blockIdx.x, h = blockIdx.y, d = threadIdx.x;
    float* base = (h < NH) ? (q + (size_t)s * (NH * HD) + h * HD)
                           : (k + (size_t)s * (NKV * HD) + (h - NH) * HD);
    float2 cs = g_cs[s * 64 + d];
    float x0 = base[d], x1 = base[d + 64];
    base[d]      = to_tf32(x0 * cs.x - x1 * cs.y);
    base[d + 64] = to_tf32(x1 * cs.x + x0 * cs.y);
}

// ---------------- softmax (tf32 probs, zero-pad to 128 boundary) -----------
__global__ __launch_bounds__(256)
void softmax_kernel(float* __restrict__ scores) {
    const int srow = blockIdx.x, h = blockIdx.y;
    float* row = scores + ((size_t)h * SEQ + srow) * SEQ;
    const int n = srow + 1;
    const int padn = ((n + 127) / 128) * 128;
    __shared__ float buf[SEQ];
    __shared__ float red[256];
    const int tid = threadIdx.x;
    float mx = -1e30f;
    for (int j = tid; j < n; j += 256) { float v = row[j]; buf[j] = v; mx = fmaxf(mx, v); }
    red[tid] = mx;
    __syncthreads();
    for (int st = 128; st > 0; st >>= 1) {
        if (tid < st) red[tid] = fmaxf(red[tid], red[tid + st]);
        __syncthreads();
    }
    mx = red[0];
    __syncthreads();
    float sum = 0.f;
    for (int j = tid; j < n; j += 256) { float e = fexp(buf[j] - mx); buf[j] = e; sum += e; }
    red[tid] = sum;
    __syncthreads();
    for (int st = 128; st > 0; st >>= 1) {
        if (tid < st) red[tid] += red[tid + st];
        __syncthreads();
    }
    const float inv = 1.0f / red[0];
    for (int j = tid; j < padn; j += 256)
        row[j] = (j < n) ? to_tf32(buf[j] * inv) : 0.0f;
}

// ---------------------------------------------------------------------------
// mma.sync tf32 GEMM, 3-stage cp.async ring, one barrier per k-tile.
//   BT=true : B is [N,K] K-major (NT), ldmatrix B fragments (pre-rounded data)
//   BT=false: B is [K,N] row-major (NN), scalar-LDS B fragments + cvt.rna
// BM=128, BN=128, BK=32, 256 threads (8 warps, 2x4), warp tile 64x32.
// EPI: 0 fp32 store, 1 +Aux, 2 *scale causal, 3 tf32(silu(Aux)*acc), 4 tf32.
// ---------------------------------------------------------------------------
constexpr int TSA = 36;                 // A smem row stride (floats)
constexpr int ASZ = 128 * TSA;          // A tile floats
constexpr int TSBT = 36;                // B stride, NT layout
constexpr int BSZT = 128 * TSBT;
constexpr int TSBN = 136;               // B stride, NN layout (136 % 32 == 8)
constexpr int BSZN = 32 * TSBN;
constexpr int NSTAGE = 3;

template<int EPI, bool CAUSAL, bool CK, bool BT>
__global__ __launch_bounds__(256, 2)
void mma_gemm(const float* __restrict__ A, const float* __restrict__ B,
              float* __restrict__ C, const float* __restrict__ Aux,
              int K, int lda, int ldb, int ldc,
              long zA, long zB, long zC, int bGroup, float scale) {
    const int row0 = blockIdx.y * 128;
    const int col0 = blockIdx.x * 128;
    if (CAUSAL && col0 > row0 + 127) return;
    const int bz = blockIdx.z;
    A += (size_t)bz * zA;
    B += (size_t)(bz / bGroup) * zB;
    C += (size_t)bz * zC;
    if (EPI == 1 || EPI == 3) Aux += (size_t)bz * zC;

    constexpr int BSZ = BT ? BSZT : BSZN;
    constexpr int STG = ASZ + BSZ;

    extern __shared__ float sm[];
    const uint32_t smBase = smem_u32(sm);

    const int tid = threadIdx.x;
    const int wid = tid >> 5, lane = tid & 31;
    const int lr = lane >> 2, lc = lane & 3;
    const int wm = (wid & 1) * 64;
    const int wn = (wid >> 1) * 32;

    const int nkt = CK ? (row0 + 128) / 32 : K / 32;

    // ldmatrix per-thread offsets (floats)
    const int qd = lane >> 3, rq = lane & 7;
    const uint32_t aRowOff = (uint32_t)((wm + (qd & 1) * 8 + rq) * TSA + (qd >> 1) * 4);
    const int bHalf = (lane >> 4) & 1, bSub = (lane >> 3) & 1;
    const uint32_t bRowOff = (uint32_t)((wn + bHalf * 8 + rq) * TSBT + bSub * 4);

    auto stage = [&](int s, int kt) {
        const uint32_t aB = smBase + (uint32_t)(s * STG) * 4;
        const uint32_t bB = aB + (uint32_t)ASZ * 4;
        const float* Ap = A + (size_t)row0 * lda + kt * 32;
#pragma unroll
        for (int j = 0; j < 4; j++) {
            int idx = j * 256 + tid, r = idx >> 3, c4 = idx & 7;
            cp16(aB + (uint32_t)(r * TSA + c4 * 4) * 4, Ap + (size_t)r * lda + c4 * 4);
        }
        if (BT) {
            const float* Bp = B + (size_t)col0 * ldb + kt * 32;
#pragma unroll
            for (int j = 0; j < 4; j++) {
                int idx = j * 256 + tid, r = idx >> 3, c4 = idx & 7;
                cp16(bB + (uint32_t)(r * TSBT + c4 * 4) * 4, Bp + (size_t)r * ldb + c4 * 4);
            }
        } else {
            const float* Bp = B + (size_t)(kt * 32) * ldb + col0;
#pragma unroll
            for (int j = 0; j < 4; j++) {
                int idx = j * 256 + tid, r = idx >> 5, c4 = idx & 31;
                cp16(bB + (uint32_t)(r * TSBN + c4 * 4) * 4, Bp + (size_t)r * ldb + c4 * 4);
            }
        }
    };

    float acc[4][4][4];
#pragma unroll
    for (int mt = 0; mt < 4; mt++)
#pragma unroll
        for (int nt = 0; nt < 4; nt++)
#pragma unroll
            for (int i = 0; i < 4; i++) acc[mt][nt][i] = 0.f;

    stage(0, 0);
    cp_commit();
    if (nkt > 1) { stage(1, 1); cp_commit(); }

    int s = 0;
    for (int kt = 0; kt < nkt; kt++) {
        if (kt == nkt - 1) cp_wait<0>(); else cp_wait<1>();
        __syncthreads();
        if (kt + 2 < nkt) {
            int s2 = s + 2; if (s2 >= NSTAGE) s2 -= NSTAGE;
            stage(s2, kt + 2);
            cp_commit();
        }

        const uint32_t aB4 = smBase + (uint32_t)(s * STG) * 4;
        const float* b_s = sm + s * STG + ASZ;
        const uint32_t bB4 = aB4 + (uint32_t)ASZ * 4;
#pragma unroll
        for (int ks = 0; ks < 4; ks++) {
            uint32_t af[4][4], bf[4][2];
#pragma unroll
            for (int mt = 0; mt < 4; mt++)
                ldsm_x4(af[mt], aB4 + (aRowOff + (uint32_t)(mt * 16 * TSA + ks * 8)) * 4);
            if (BT) {
#pragma unroll
                for (int ntp = 0; ntp < 2; ntp++) {
                    uint32_t tmp[4];
                    ldsm_x4(tmp, bB4 + (bRowOff + (uint32_t)(ntp * 16 * TSBT + ks * 8)) * 4);
                    bf[ntp * 2][0] = tmp[0]; bf[ntp * 2][1] = tmp[1];
                    bf[ntp * 2 + 1][0] = tmp[2]; bf[ntp * 2 + 1][1] = tmp[3];
                }
            } else {
#pragma unroll
                for (int nt = 0; nt < 4; nt++) {
                    const int n = wn + nt * 8 + lr;
                    bf[nt][0] = to_tf32_u(b_s[(ks * 8 + lc) * TSBN + n]);
                    bf[nt][1] = to_tf32_u(b_s[(ks * 8 + lc + 4) * TSBN + n]);
                }
            }
#pragma unroll
            for (int mt = 0; mt < 4; mt++)
#pragma unroll
                for (int nt = 0; nt < 4; nt++)
                    mma_tf32(acc[mt][nt], af[mt], bf[nt]);
        }
        if (++s >= NSTAGE) s -= NSTAGE;
    }

    // -------- epilogue
#pragma unroll
    for (int mt = 0; mt < 4; mt++) {
        const int ra = row0 + wm + mt * 16 + lr;
        const int rb = ra + 8;
#pragma unroll
        for (int nt = 0; nt < 4; nt++) {
            const int c = col0 + wn + nt * 8 + lc * 2;
            float* acc4 = acc[mt][nt];
            const size_t ia = (size_t)ra * ldc + c;
            const size_t ib = (size_t)rb * ldc + c;
            if (EPI == 0) {
                *(float2*)&C[ia] = make_float2(acc4[0], acc4[1]);
                *(float2*)&C[ib] = make_float2(acc4[2], acc4[3]);
            } else if (EPI == 1) {
                float2 xa = *(const float2*)&Aux[ia], xb = *(const float2*)&Aux[ib];
                *(float2*)&C[ia] = make_float2(acc4[0] + xa.x, acc4[1] + xa.y);
                *(float2*)&C[ib] = make_float2(acc4[2] + xb.x, acc4[3] + xb.y);
            } else if (EPI == 2) {
                if (c     <= ra) C[ia]     = acc4[0] * scale;
                if (c + 1 <= ra) C[ia + 1] = acc4[1] * scale;
                if (c     <= rb) C[ib]     = acc4[2] * scale;
                if (c + 1 <= rb) C[ib + 1] = acc4[3] * scale;
            } else if (EPI == 3) {
                float2 ga = *(const float2*)&Aux[ia], gb = *(const float2*)&Aux[ib];
                *(float2*)&C[ia] = make_float2(to_tf32(acc4[0] * silu(ga.x)),
                                               to_tf32(acc4[1] * silu(ga.y)));
                *(float2*)&C[ib] = make_float2(to_tf32(acc4[2] * silu(gb.x)),
                                               to_tf32(acc4[3] * silu(gb.y)));
            } else {  // EPI == 4
                *(float2*)&C[ia] = make_float2(to_tf32(acc4[0]), to_tf32(acc4[1]));
                *(float2*)&C[ib] = make_float2(to_tf32(acc4[2]), to_tf32(acc4[3]));
            }
        }
    }
}

// ---------------------------------------------------------------------------
extern "C" void kernel_launch(void* const* d_in, const int* in_sizes, int n_in,
                              void* d_out, int out_size) {
    (void)in_sizes; (void)n_in; (void)out_size;
    const float* x   = (const float*)d_in[0];
    const float* ln1 = (const float*)d_in[2];
    const float* Wq  = (const float*)d_in[3];
    const float* Wk  = (const float*)d_in[4];
    const float* Wv  = (const float*)d_in[5];
    const float* Wo  = (const float*)d_in[6];
    const float* ln2 = (const float*)d_in[7];
    const float* Wg  = (const float*)d_in[8];
    const float* Wu  = (const float*)d_in[9];
    const float* Wd  = (const float*)d_in[10];
    float* out = (float*)d_out;

    float *h1, *q, *k, *v, *sc, *at, *x2, *h2, *gg, *mm;
    cudaGetSymbolAddress((void**)&h1, g_h1);   cudaGetSymbolAddress((void**)&q, g_q);
    cudaGetSymbolAddress((void**)&k, g_k);     cudaGetSymbolAddress((void**)&v, g_v);
    cudaGetSymbolAddress((void**)&sc, g_sc);   cudaGetSymbolAddress((void**)&at, g_at);
    cudaGetSymbolAddress((void**)&x2, g_x2);   cudaGetSymbolAddress((void**)&h2, g_h2);
    cudaGetSymbolAddress((void**)&gg, g_gg);   cudaGetSymbolAddress((void**)&mm, g_mm);

    const int SMEM_NT = NSTAGE * (ASZ + BSZT) * 4;
    const int SMEM_NN = NSTAGE * (ASZ + BSZN) * 4;
    cudaFuncSetAttribute(mma_gemm<0, false, false, false>, cudaFuncAttributeMaxDynamicSharedMemorySize, SMEM_NN);
    cudaFuncSetAttribute(mma_gemm<1, false, false, false>, cudaFuncAttributeMaxDynamicSharedMemorySize, SMEM_NN);
    cudaFuncSetAttribute(mma_gemm<3, false, false, false>, cudaFuncAttributeMaxDynamicSharedMemorySize, SMEM_NN);
    cudaFuncSetAttribute(mma_gemm<4, false, true,  false>, cudaFuncAttributeMaxDynamicSharedMemorySize, SMEM_NN);
    cudaFuncSetAttribute(mma_gemm<2, true,  false, true >, cudaFuncAttributeMaxDynamicSharedMemorySize, SMEM_NT);

    const float iscale = 0.08838834764831843f;  // 1/sqrt(128)

    init_invf_kernel<<<1, 64>>>();
    rope_table_kernel<<<SEQ, 64>>>();
    rmsnorm_kernel<<<SEQ, 256>>>(x, ln1, h1);

    // projections (NN: B = original [K,N] weights, cvt.rna in-kernel)
    mma_gemm<0, false, false, false><<<dim3(16, 16, 1), 256, SMEM_NN>>>(
        h1, Wq, q, nullptr, DIM, DIM, DIM, DIM, 0, 0, 0, 1, 0.f);
    mma_gemm<0, false, false, false><<<dim3(4, 16, 1), 256, SMEM_NN>>>(
        h1, Wk, k, nullptr, DIM, DIM, 512, 512, 0, 0, 0, 1, 0.f);
    mma_gemm<0, false, false, false><<<dim3(4, 16, 1), 256, SMEM_NN>>>(
        h1, Wv, v, nullptr, DIM, DIM, 512, 512, 0, 0, 0, 1, 0.f);

    rope_apply_kernel<<<dim3(SEQ, NH + NKV), 64>>>(q, k);

    // scores = causal(q @ k^T) * iscale  (NT: both K-major, pre-rounded)
    mma_gemm<2, true, false, true><<<dim3(16, 16, NH), 256, SMEM_NT>>>(
        q, k, sc, nullptr, HD, DIM, 512, SEQ,
        HD, HD, (long)SEQ * SEQ, NKV, iscale);

    softmax_kernel<<<dim3(SEQ, NH), 256>>>(sc);

    // at = probs @ v   (NN with per-head column offset into v; causal K-limit)
    mma_gemm<4, false, true, false><<<dim3(1, 16, NH), 256, SMEM_NN>>>(
        sc, v, at, nullptr, SEQ, SEQ, 512, DIM,
        (long)SEQ * SEQ, (long)HD, HD, NKV, 0.f);

    // x2 = at @ Wo + x
    mma_gemm<1, false, false, false><<<dim3(16, 16, 1), 256, SMEM_NN>>>(
        at, Wo, x2, x, DIM, DIM, DIM, DIM, 0, 0, 0, 1, 0.f);

    rmsnorm_kernel<<<SEQ, 256>>>(x2, ln2, h2);

    // MLP
    mma_gemm<0, false, false, false><<<dim3(64, 16, 1), 256, SMEM_NN>>>(
        h2, Wg, gg, nullptr, DIM, DIM, FF, FF, 0, 0, 0, 1, 0.f);
    mma_gemm<3, false, false, false><<<dim3(64, 16, 1), 256, SMEM_NN>>>(
        h2, Wu, mm, gg, DIM, DIM, FF, FF, 0, 0, 0, 1, 0.f);
    mma_gemm<1, false, false, false><<<dim3(16, 16, 1), 256, SMEM_NN>>>(
        mm, Wd, out, x2, FF, FF, DIM, DIM, 0, 0, 0, 1, 0.f);
}

// round 9
// speedup vs baseline: 1.0144x; 1.0144x over previous
#include <cuda_runtime.h>
#include <cstdint>
#include <math.h>

constexpr int SEQ = 2048, DIM = 2048, NH = 16, NKV = 4, HD = 128, FF = 8192;
constexpr float EPSV = 1e-6f;

// ---------------------------------------------------------------------------
// Scratch (device globals — allocation forbidden)
// ---------------------------------------------------------------------------
__device__ float g_h1[SEQ * DIM];
__device__ float g_q [SEQ * NH * HD];
__device__ float g_k [SEQ * NKV * HD];
__device__ float g_v [SEQ * NKV * HD];
__device__ float g_vT[NKV * HD * SEQ];
__device__ float g_sc[(long)NH * SEQ * SEQ];
__device__ float g_at[SEQ * NH * HD];
__device__ float g_x2[SEQ * DIM];
__device__ float g_h2[SEQ * DIM];
__device__ float g_gg[(long)SEQ * FF];
__device__ float g_mm[(long)SEQ * FF];
__device__ float g_WqT[DIM * DIM];
__device__ float g_WkT[NKV * HD * DIM];
__device__ float g_WvT[NKV * HD * DIM];
__device__ float g_WoT[DIM * DIM];
__device__ float g_WgT[(long)FF * DIM];
__device__ float g_WuT[(long)FF * DIM];
__device__ float g_WdT[(long)DIM * FF];
__device__ double g_invf[64];
__device__ float2 g_cs[SEQ * 64];

// ---------------------------------------------------------------------------
__device__ __forceinline__ uint32_t smem_u32(const void* p) {
    uint32_t a;
    asm("{ .reg .u64 t; cvta.to.shared.u64 t, %1; cvt.u32.u64 %0, t; }" : "=r"(a) : "l"(p));
    return a;
}
__device__ __forceinline__ float to_tf32(float x) {
    uint32_t u;
    asm("cvt.rna.tf32.f32 %0, %1;" : "=r"(u) : "f"(x));
    return __uint_as_float(u);
}
__device__ __forceinline__ void cp16(uint32_t dst, const void* src) {
    asm volatile("cp.async.cg.shared.global [%0], [%1], 16;" :: "r"(dst), "l"(src) : "memory");
}
__device__ __forceinline__ void cp_commit() {
    asm volatile("cp.async.commit_group;" ::: "memory");
}
template<int N> __device__ __forceinline__ void cp_wait() {
    asm volatile("cp.async.wait_group %0;" :: "n"(N) : "memory");
}
__device__ __forceinline__ void mma_tf32(float* c, const uint32_t* a, const uint32_t* b) {
    asm volatile(
        "mma.sync.aligned.m16n8k8.row.col.f32.tf32.tf32.f32 "
        "{%0,%1,%2,%3}, {%4,%5,%6,%7}, {%8,%9}, {%0,%1,%2,%3};"
        : "+f"(c[0]), "+f"(c[1]), "+f"(c[2]), "+f"(c[3])
        : "r"(a[0]), "r"(a[1]), "r"(a[2]), "r"(a[3]), "r"(b[0]), "r"(b[1]));
}
__device__ __forceinline__ void ldsm_x4(uint32_t* r, uint32_t addr) {
    asm volatile("ldmatrix.sync.aligned.m8n8.x4.shared.b16 {%0,%1,%2,%3}, [%4];"
                 : "=r"(r[0]), "=r"(r[1]), "=r"(r[2]), "=r"(r[3]) : "r"(addr));
}

__device__ __forceinline__ float fexp(float x) {  // accurate for x <= 0
    float t = x * 1.4426950408889634f;
    float r = rintf(t), f = t - r;
    int i = (int)r;
    float p = 0.0013333558f;
    p = fmaf(p, f, 0.0096181291f);
    p = fmaf(p, f, 0.0555041087f);
    p = fmaf(p, f, 0.2402264476f);
    p = fmaf(p, f, 0.6931471806f);
    p = fmaf(p, f, 1.0f);
    float s = __int_as_float((i + 127) << 23);
    return (x < -80.f) ? 0.f : p * s;
}
__device__ __forceinline__ float silu(float g) {
    float t = fexp(-fabsf(g));
    float s = (g >= 0.f) ? 1.f / (1.f + t) : t / (1.f + t);
    return g * s;
}

// ---------------- fast transpose + tf32 round: out[C,R] = rna(in[R,C]^T) ---
// 64x64 tiles. float4 for GLOBAL loads/stores; scalar smem (stride 65) to
// avoid misaligned 128-bit STS (65*4 = 260 B row stride is not 16B-aligned).
__global__ __launch_bounds__(256)
void transpose_f4(const float* __restrict__ in, float* __restrict__ out, int R, int C) {
    __shared__ float tb[64][65];
    const int rb = blockIdx.y * 64, cb = blockIdx.x * 64;
    const int tr = threadIdx.x >> 4;          // 0..15
    const int c4 = (threadIdx.x & 15) * 4;    // 0..60
#pragma unroll
    for (int i = 0; i < 4; i++) {
        int r = tr + i * 16;
        float4 v = *(const float4*)&in[(size_t)(rb + r) * C + cb + c4];
        tb[r][c4 + 0] = to_tf32(v.x);
        tb[r][c4 + 1] = to_tf32(v.y);
        tb[r][c4 + 2] = to_tf32(v.z);
        tb[r][c4 + 3] = to_tf32(v.w);
    }
    __syncthreads();
#pragma unroll
    for (int i = 0; i < 4; i++) {
        int r = tr + i * 16;  // output row (original column)
        float4 v = make_float4(tb[c4 + 0][r], tb[c4 + 1][r], tb[c4 + 2][r], tb[c4 + 3][r]);
        *(float4*)&out[(size_t)(cb + r) * R + rb + c4] = v;
    }
}

// ---------------- rmsnorm (tf32-rounded out) -------------------------------
__global__ __launch_bounds__(256)
void rmsnorm_kernel(const float* __restrict__ x, const float* __restrict__ w,
                    float* __restrict__ o) {
    const int row = blockIdx.x;
    const float* xr = x + (size_t)row * DIM;
    float s = 0.f;
    for (int j = threadIdx.x; j < DIM; j += 256) { float v = xr[j]; s += v * v; }
    __shared__ float red[256];
    red[threadIdx.x] = s;
    __syncthreads();
    for (int st = 128; st > 0; st >>= 1) {
        if (threadIdx.x < st) red[threadIdx.x] += red[threadIdx.x + st];
        __syncthreads();
    }
    const float inv = rsqrtf(red[0] * (1.0f / DIM) + EPSV);
    float* orow = o + (size_t)row * DIM;
    for (int j = threadIdx.x; j < DIM; j += 256)
        orow[j] = to_tf32(xr[j] * inv * w[j]);
}

// ---------------- RoPE -----------------------------------------------------
__global__ void init_invf_kernel() { g_invf[threadIdx.x] = pow(10000.0, -(double)threadIdx.x / 64.0); }
__global__ void rope_table_kernel() {
    int s = blockIdx.x, d = threadIdx.x;
    double ang = (double)s * g_invf[d];
    const double twopi = 6.283185307179586476925287;
    double r = ang - twopi * floor(ang / twopi + 0.5);
    float rf = (float)r;
    g_cs[s * 64 + d] = make_float2(cosf(rf), sinf(rf));
}
__global__ void rope_apply_kernel(float* __restrict__ q, float* __restrict__ k) {
    const int s = blockIdx.x, h = blockIdx.y, d = threadIdx.x;
    float* base = (h < NH) ? (q + (size_t)s * (NH * HD) + h * HD)
                           : (k + (size_t)s * (NKV * HD) + (h - NH) * HD);
    float2 cs = g_cs[s * 64 + d];
    float x0 = base[d], x1 = base[d + 64];
    base[d]      = to_tf32(x0 * cs.x - x1 * cs.y);
    base[d + 64] = to_tf32(x1 * cs.x + x0 * cs.y);
}

// ---------------- softmax (tf32 probs, zero-pad to 128 boundary) -----------
__global__ __launch_bounds__(256)
void softmax_kernel(float* __restrict__ scores) {
    const int srow = blockIdx.x, h = blockIdx.y;
    float* row = scores + ((size_t)h * SEQ + srow) * SEQ;
    const int n = srow + 1;
    const int padn = ((n + 127) / 128) * 128;
    __shared__ float buf[SEQ];
    __shared__ float red[256];
    const int tid = threadIdx.x;
    float mx = -1e30f;
    for (int j = tid; j < n; j += 256) { float v = row[j]; buf[j] = v; mx = fmaxf(mx, v); }
    red[tid] = mx;
    __syncthreads();
    for (int st = 128; st > 0; st >>= 1) {
        if (tid < st) red[tid] = fmaxf(red[tid], red[tid + st]);
        __syncthreads();
    }
    mx = red[0];
    __syncthreads();
    float sum = 0.f;
    for (int j = tid; j < n; j += 256) { float e = fexp(buf[j] - mx); buf[j] = e; sum += e; }
    red[tid] = sum;
    __syncthreads();
    for (int st = 128; st > 0; st >>= 1) {
        if (tid < st) red[tid] += red[tid + st];
        __syncthreads();
    }
    const float inv = 1.0f / red[0];
    for (int j = tid; j < padn; j += 256)
        row[j] = (j < n) ? to_tf32(buf[j] * inv) : 0.0f;
}

// ---------------------------------------------------------------------------
// mma.sync tf32 GEMM (NT): C[M,N] = A[M,K] @ B[N,K]^T, both K-major,
// inputs pre-rounded to tf32. ldmatrix fragments, double-buffered per-ks.
// 3-stage cp.async ring, one barrier per k-tile.
// BM=128, BN=128, BK=32, 256 threads (8 warps, 2x4), warp tile 64x32.
// EPI: 0 fp32 store, 1 +Aux, 2 *scale causal, 3 tf32(silu(Aux)*acc), 4 tf32.
// ---------------------------------------------------------------------------
constexpr int TSA = 36;                 // smem row stride (floats)
constexpr int ASZ = 128 * TSA;
constexpr int BSZ = 128 * TSA;
constexpr int STG = ASZ + BSZ;
constexpr int NSTAGE = 3;
constexpr int GEMM_SMEM = NSTAGE * STG * 4;   // 110,592 B

template<int EPI, bool CAUSAL, bool CK>
__global__ __launch_bounds__(256, 2)
void mma_gemm(const float* __restrict__ A, const float* __restrict__ B,
              float* __restrict__ C, const float* __restrict__ Aux,
              int K, int lda, int ldb, int ldc,
              long zA, long zB, long zC, int bGroup, float scale) {
    const int row0 = blockIdx.y * 128;
    const int col0 = blockIdx.x * 128;
    if (CAUSAL && col0 > row0 + 127) return;
    const int bz = blockIdx.z;
    A += (size_t)bz * zA;
    B += (size_t)(bz / bGroup) * zB;
    C += (size_t)bz * zC;
    if (EPI == 1 || EPI == 3) Aux += (size_t)bz * zC;

    extern __shared__ float sm[];
    const uint32_t smBase = smem_u32(sm);

    const int tid = threadIdx.x;
    const int wid = tid >> 5, lane = tid & 31;
    const int lr = lane >> 2, lc = lane & 3;
    const int wm = (wid & 1) * 64;
    const int wn = (wid >> 1) * 32;

    const int nkt = CK ? (row0 + 128) / 32 : K / 32;

    // ldmatrix per-thread offsets (floats)
    const int qd = lane >> 3, rq = lane & 7;
    const uint32_t aRowOff = (uint32_t)((wm + (qd & 1) * 8 + rq) * TSA + (qd >> 1) * 4);
    const int bHalf = (lane >> 4) & 1, bSub = (lane >> 3) & 1;
    const uint32_t bRowOff = (uint32_t)((wn + bHalf * 8 + rq) * TSA + bSub * 4);

    auto stage = [&](int s, int kt) {
        const uint32_t aB = smBase + (uint32_t)(s * STG) * 4;
        const uint32_t bB = aB + (uint32_t)ASZ * 4;
        const float* Ap = A + (size_t)row0 * lda + kt * 32;
        const float* Bp = B + (size_t)col0 * ldb + kt * 32;
#pragma unroll
        for (int j = 0; j < 4; j++) {
            int idx = j * 256 + tid, r = idx >> 3, c4 = idx & 7;
            cp16(aB + (uint32_t)(r * TSA + c4 * 4) * 4, Ap + (size_t)r * lda + c4 * 4);
        }
#pragma unroll
        for (int j = 0; j < 4; j++) {
            int idx = j * 256 + tid, r = idx >> 3, c4 = idx & 7;
            cp16(bB + (uint32_t)(r * TSA + c4 * 4) * 4, Bp + (size_t)r * ldb + c4 * 4);
        }
    };

    float acc[4][4][4];
#pragma unroll
    for (int mt = 0; mt < 4; mt++)
#pragma unroll
        for (int nt = 0; nt < 4; nt++)
#pragma unroll
            for (int i = 0; i < 4; i++) acc[mt][nt][i] = 0.f;

    stage(0, 0);
    cp_commit();
    if (nkt > 1) { stage(1, 1); cp_commit(); }

    uint32_t af[2][4][4], bf[2][4][2];

    auto loadFrags = [&](int buf, int ks, uint32_t aB4, uint32_t bB4) {
#pragma unroll
        for (int mt = 0; mt < 4; mt++)
            ldsm_x4(af[buf][mt], aB4 + (aRowOff + (uint32_t)(mt * 16 * TSA + ks * 8)) * 4);
#pragma unroll
        for (int ntp = 0; ntp < 2; ntp++) {
            uint32_t tmp[4];
            ldsm_x4(tmp, bB4 + (bRowOff + (uint32_t)(ntp * 16 * TSA + ks * 8)) * 4);
            bf[buf][ntp * 2][0] = tmp[0]; bf[buf][ntp * 2][1] = tmp[1];
            bf[buf][ntp * 2 + 1][0] = tmp[2]; bf[buf][ntp * 2 + 1][1] = tmp[3];
        }
    };

    int s = 0;
    for (int kt = 0; kt < nkt; kt++) {
        if (kt == nkt - 1) cp_wait<0>(); else cp_wait<1>();
        __syncthreads();
        if (kt + 2 < nkt) {
            int s2 = s + 2; if (s2 >= NSTAGE) s2 -= NSTAGE;
            stage(s2, kt + 2);
            cp_commit();
        }

        const uint32_t aB4 = smBase + (uint32_t)(s * STG) * 4;
        const uint32_t bB4 = aB4 + (uint32_t)ASZ * 4;
        loadFrags(0, 0, aB4, bB4);
#pragma unroll
        for (int ks = 0; ks < 4; ks++) {
            if (ks < 3) loadFrags((ks + 1) & 1, ks + 1, aB4, bB4);
            const int cb = ks & 1;
#pragma unroll
            for (int mt = 0; mt < 4; mt++)
#pragma unroll
                for (int nt = 0; nt < 4; nt++)
                    mma_tf32(acc[mt][nt], af[cb][mt], bf[cb][nt]);
        }
        if (++s >= NSTAGE) s -= NSTAGE;
    }

    // -------- epilogue
#pragma unroll
    for (int mt = 0; mt < 4; mt++) {
        const int ra = row0 + wm + mt * 16 + lr;
        const int rb = ra + 8;
#pragma unroll
        for (int nt = 0; nt < 4; nt++) {
            const int c = col0 + wn + nt * 8 + lc * 2;
            float* acc4 = acc[mt][nt];
            const size_t ia = (size_t)ra * ldc + c;
            const size_t ib = (size_t)rb * ldc + c;
            if (EPI == 0) {
                *(float2*)&C[ia] = make_float2(acc4[0], acc4[1]);
                *(float2*)&C[ib] = make_float2(acc4[2], acc4[3]);
            } else if (EPI == 1) {
                float2 xa = *(const float2*)&Aux[ia], xb = *(const float2*)&Aux[ib];
                *(float2*)&C[ia] = make_float2(acc4[0] + xa.x, acc4[1] + xa.y);
                *(float2*)&C[ib] = make_float2(acc4[2] + xb.x, acc4[3] + xb.y);
            } else if (EPI == 2) {
                if (c     <= ra) C[ia]     = acc4[0] * scale;
                if (c + 1 <= ra) C[ia + 1] = acc4[1] * scale;
                if (c     <= rb) C[ib]     = acc4[2] * scale;
                if (c + 1 <= rb) C[ib + 1] = acc4[3] * scale;
            } else if (EPI == 3) {
                float2 ga = *(const float2*)&Aux[ia], gb = *(const float2*)&Aux[ib];
                *(float2*)&C[ia] = make_float2(to_tf32(acc4[0] * silu(ga.x)),
                                               to_tf32(acc4[1] * silu(ga.y)));
                *(float2*)&C[ib] = make_float2(to_tf32(acc4[2] * silu(gb.x)),
                                               to_tf32(acc4[3] * silu(gb.y)));
            } else {  // EPI == 4
                *(float2*)&C[ia] = make_float2(to_tf32(acc4[0]), to_tf32(acc4[1]));
                *(float2*)&C[ib] = make_float2(to_tf32(acc4[2]), to_tf32(acc4[3]));
            }
        }
    }
}

// ---------------------------------------------------------------------------
extern "C" void kernel_launch(void* const* d_in, const int* in_sizes, int n_in,
                              void* d_out, int out_size) {
    (void)in_sizes; (void)n_in; (void)out_size;
    const float* x   = (const float*)d_in[0];
    const float* ln1 = (const float*)d_in[2];
    const float* Wq  = (const float*)d_in[3];
    const float* Wk  = (const float*)d_in[4];
    const float* Wv  = (const float*)d_in[5];
    const float* Wo  = (const float*)d_in[6];
    const float* ln2 = (const float*)d_in[7];
    const float* Wg  = (const float*)d_in[8];
    const float* Wu  = (const float*)d_in[9];
    const float* Wd  = (const float*)d_in[10];
    float* out = (float*)d_out;

    float *h1, *q, *k, *v, *vT, *sc, *at, *x2, *h2, *gg, *mm;
    float *WqT, *WkT, *WvT, *WoT, *WgT, *WuT, *WdT;
    cudaGetSymbolAddress((void**)&h1, g_h1);   cudaGetSymbolAddress((void**)&q, g_q);
    cudaGetSymbolAddress((void**)&k, g_k);     cudaGetSymbolAddress((void**)&v, g_v);
    cudaGetSymbolAddress((void**)&vT, g_vT);   cudaGetSymbolAddress((void**)&sc, g_sc);
    cudaGetSymbolAddress((void**)&at, g_at);   cudaGetSymbolAddress((void**)&x2, g_x2);
    cudaGetSymbolAddress((void**)&h2, g_h2);   cudaGetSymbolAddress((void**)&gg, g_gg);
    cudaGetSymbolAddress((void**)&mm, g_mm);
    cudaGetSymbolAddress((void**)&WqT, g_WqT); cudaGetSymbolAddress((void**)&WkT, g_WkT);
    cudaGetSymbolAddress((void**)&WvT, g_WvT); cudaGetSymbolAddress((void**)&WoT, g_WoT);
    cudaGetSymbolAddress((void**)&WgT, g_WgT); cudaGetSymbolAddress((void**)&WuT, g_WuT);
    cudaGetSymbolAddress((void**)&WdT, g_WdT);

    cudaFuncSetAttribute(mma_gemm<0, false, false>, cudaFuncAttributeMaxDynamicSharedMemorySize, GEMM_SMEM);
    cudaFuncSetAttribute(mma_gemm<1, false, false>, cudaFuncAttributeMaxDynamicSharedMemorySize, GEMM_SMEM);
    cudaFuncSetAttribute(mma_gemm<2, true,  false>, cudaFuncAttributeMaxDynamicSharedMemorySize, GEMM_SMEM);
    cudaFuncSetAttribute(mma_gemm<3, false, false>, cudaFuncAttributeMaxDynamicSharedMemorySize, GEMM_SMEM);
    cudaFuncSetAttribute(mma_gemm<4, false, true >, cudaFuncAttributeMaxDynamicSharedMemorySize, GEMM_SMEM);

    const float iscale = 0.08838834764831843f;  // 1/sqrt(128)

    // weight transposes (+ tf32 rounding), float4 global traffic
    transpose_f4<<<dim3(DIM / 64, DIM / 64), 256>>>(Wq, WqT, DIM, DIM);
    transpose_f4<<<dim3(512 / 64, DIM / 64), 256>>>(Wk, WkT, DIM, 512);
    transpose_f4<<<dim3(512 / 64, DIM / 64), 256>>>(Wv, WvT, DIM, 512);
    transpose_f4<<<dim3(DIM / 64, DIM / 64), 256>>>(Wo, WoT, DIM, DIM);
    transpose_f4<<<dim3(FF / 64, DIM / 64), 256>>>(Wg, WgT, DIM, FF);
    transpose_f4<<<dim3(FF / 64, DIM / 64), 256>>>(Wu, WuT, DIM, FF);
    transpose_f4<<<dim3(DIM / 64, FF / 64), 256>>>(Wd, WdT, FF, DIM);
    init_invf_kernel<<<1, 64>>>();
    rope_table_kernel<<<SEQ, 64>>>();

    rmsnorm_kernel<<<SEQ, 256>>>(x, ln1, h1);

    // projections (NT, transposed weights)
    mma_gemm<0, false, false><<<dim3(16, 16, 1), 256, GEMM_SMEM>>>(
        h1, WqT, q, nullptr, DIM, DIM, DIM, DIM, 0, 0, 0, 1, 0.f);
    mma_gemm<0, false, false><<<dim3(4, 16, 1), 256, GEMM_SMEM>>>(
        h1, WkT, k, nullptr, DIM, DIM, DIM, 512, 0, 0, 0, 1, 0.f);
    mma_gemm<0, false, false><<<dim3(4, 16, 1), 256, GEMM_SMEM>>>(
        h1, WvT, v, nullptr, DIM, DIM, DIM, 512, 0, 0, 0, 1, 0.f);
    transpose_f4<<<dim3(512 / 64, SEQ / 64), 256>>>(v, vT, SEQ, 512);

    rope_apply_kernel<<<dim3(SEQ, NH + NKV), 64>>>(q, k);

    // scores = causal(q @ k^T) * iscale
    mma_gemm<2, true, false><<<dim3(16, 16, NH), 256, GEMM_SMEM>>>(
        q, k, sc, nullptr, HD, DIM, 512, SEQ,
        HD, HD, (long)SEQ * SEQ, NKV, iscale);

    softmax_kernel<<<dim3(SEQ, NH), 256>>>(sc);

    // at = probs @ v  (NT via vT, causal K-limit)
    mma_gemm<4, false, true><<<dim3(1, 16, NH), 256, GEMM_SMEM>>>(
        sc, vT, at, nullptr, SEQ, SEQ, SEQ, DIM,
        (long)SEQ * SEQ, (long)HD * SEQ, HD, NKV, 0.f);

    // x2 = at @ Wo + x
    mma_gemm<1, false, false><<<dim3(16, 16, 1), 256, GEMM_SMEM>>>(
        at, WoT, x2, x, DIM, DIM, DIM, DIM, 0, 0, 0, 1, 0.f);

    rmsnorm_kernel<<<SEQ, 256>>>(x2, ln2, h2);

    // MLP
    mma_gemm<0, false, false><<<dim3(64, 16, 1), 256, GEMM_SMEM>>>(
        h2, WgT, gg, nullptr, DIM, DIM, DIM, FF, 0, 0, 0, 1, 0.f);
    mma_gemm<3, false, false><<<dim3(64, 16, 1), 256, GEMM_SMEM>>>(
        h2, WuT, mm, gg, DIM, DIM, DIM, FF, 0, 0, 0, 1, 0.f);
    mma_gemm<1, false, false><<<dim3(16, 16, 1), 256, GEMM_SMEM>>>(
        mm, WdT, out, x2, FF, FF, FF, DIM, 0, 0, 0, 1, 0.f);
}

// round 10
// speedup vs baseline: 1.9333x; 1.9058x over previous
#include <cuda_runtime.h>
#include <cuda_fp16.h>
#include <cstdint>
#include <math.h>

constexpr int SEQ = 2048, DIM = 2048, NH = 16, NKV = 4, HD = 128, FF = 8192;
constexpr float EPSV = 1e-6f;

// ---------------------------------------------------------------------------
// Scratch (device globals — allocation forbidden)
// ---------------------------------------------------------------------------
__device__ __half g_h1h[SEQ * DIM];
__device__ __half g_qh [SEQ * NH * HD];
__device__ __half g_kh [SEQ * NKV * HD];
__device__ __half g_vh [SEQ * NKV * HD];
__device__ __half g_vTh[NKV * HD * SEQ];
__device__ float  g_sc [(long)NH * SEQ * SEQ];   // fp32 scores
__device__ __half g_ph [(long)NH * SEQ * SEQ];   // fp16 probs
__device__ __half g_ath[SEQ * NH * HD];
__device__ float  g_x2 [SEQ * DIM];
__device__ __half g_h2h[SEQ * DIM];
__device__ float  g_gg [(long)SEQ * FF];
__device__ __half g_mmh[(long)SEQ * FF];
__device__ __half g_WqTh[DIM * DIM];
__device__ __half g_WkTh[NKV * HD * DIM];
__device__ __half g_WvTh[NKV * HD * DIM];
__device__ __half g_WoTh[DIM * DIM];
__device__ __half g_WgTh[(long)FF * DIM];
__device__ __half g_WuTh[(long)FF * DIM];
__device__ __half g_WdTh[(long)DIM * FF];
__device__ double g_invf[64];
__device__ float2 g_cs[SEQ * 64];

// ---------------------------------------------------------------------------
__device__ __forceinline__ uint32_t smem_u32(const void* p) {
    uint32_t a;
    asm("{ .reg .u64 t; cvta.to.shared.u64 t, %1; cvt.u32.u64 %0, t; }" : "=r"(a) : "l"(p));
    return a;
}
__device__ __forceinline__ void cp16(uint32_t dst, const void* src) {
    asm volatile("cp.async.cg.shared.global [%0], [%1], 16;" :: "r"(dst), "l"(src) : "memory");
}
__device__ __forceinline__ void cp_commit() {
    asm volatile("cp.async.commit_group;" ::: "memory");
}
template<int N> __device__ __forceinline__ void cp_wait() {
    asm volatile("cp.async.wait_group %0;" :: "n"(N) : "memory");
}
__device__ __forceinline__ void mma_f16(float* c, const uint32_t* a, const uint32_t* b) {
    asm volatile(
        "mma.sync.aligned.m16n8k16.row.col.f32.f16.f16.f32 "
        "{%0,%1,%2,%3}, {%4,%5,%6,%7}, {%8,%9}, {%0,%1,%2,%3};"
        : "+f"(c[0]), "+f"(c[1]), "+f"(c[2]), "+f"(c[3])
        : "r"(a[0]), "r"(a[1]), "r"(a[2]), "r"(a[3]), "r"(b[0]), "r"(b[1]));
}
__device__ __forceinline__ void ldsm_x4(uint32_t* r, uint32_t addr) {
    asm volatile("ldmatrix.sync.aligned.m8n8.x4.shared.b16 {%0,%1,%2,%3}, [%4];"
                 : "=r"(r[0]), "=r"(r[1]), "=r"(r[2]), "=r"(r[3]) : "r"(addr));
}

__device__ __forceinline__ float fexp(float x) {  // accurate for x <= 0
    float t = x * 1.4426950408889634f;
    float r = rintf(t), f = t - r;
    int i = (int)r;
    float p = 0.0013333558f;
    p = fmaf(p, f, 0.0096181291f);
    p = fmaf(p, f, 0.0555041087f);
    p = fmaf(p, f, 0.2402264476f);
    p = fmaf(p, f, 0.6931471806f);
    p = fmaf(p, f, 1.0f);
    float s = __int_as_float((i + 127) << 23);
    return (x < -80.f) ? 0.f : p * s;
}
__device__ __forceinline__ float silu(float g) {
    float t = fexp(-fabsf(g));
    float s = (g >= 0.f) ? 1.f / (1.f + t) : t / (1.f + t);
    return g * s;
}

// ---------------- transposes to fp16 ---------------------------------------
// out[C,R] = half(in[R,C]^T). 64x64 tiles, float4 global loads, scalar smem.
__global__ __launch_bounds__(256)
void transpose_wh(const float* __restrict__ in, __half* __restrict__ out, int R, int C) {
    __shared__ float tb[64][65];
    const int rb = blockIdx.y * 64, cb = blockIdx.x * 64;
    const int tr = threadIdx.x >> 4;
    const int c4 = (threadIdx.x & 15) * 4;
#pragma unroll
    for (int i = 0; i < 4; i++) {
        int r = tr + i * 16;
        float4 v = *(const float4*)&in[(size_t)(rb + r) * C + cb + c4];
        tb[r][c4 + 0] = v.x; tb[r][c4 + 1] = v.y;
        tb[r][c4 + 2] = v.z; tb[r][c4 + 3] = v.w;
    }
    __syncthreads();
#pragma unroll
    for (int i = 0; i < 4; i++) {
        int r = tr + i * 16;
        size_t o = (size_t)(cb + r) * R + rb + c4;
        *(__half2*)&out[o]     = __floats2half2_rn(tb[c4 + 0][r], tb[c4 + 1][r]);
        *(__half2*)&out[o + 2] = __floats2half2_rn(tb[c4 + 2][r], tb[c4 + 3][r]);
    }
}
// half -> half transpose (for v), scalar
__global__ __launch_bounds__(256)
void transpose_hh(const __half* __restrict__ in, __half* __restrict__ out, int R, int C) {
    __shared__ __half tb[64][65];
    const int rb = blockIdx.y * 64, cb = blockIdx.x * 64;
    const int tr = threadIdx.x >> 4;
    const int c4 = (threadIdx.x & 15) * 4;
#pragma unroll
    for (int i = 0; i < 4; i++) {
        int r = tr + i * 16;
#pragma unroll
        for (int j = 0; j < 4; j++)
            tb[r][c4 + j] = in[(size_t)(rb + r) * C + cb + c4 + j];
    }
    __syncthreads();
#pragma unroll
    for (int i = 0; i < 4; i++) {
        int r = tr + i * 16;
        size_t o = (size_t)(cb + r) * R + rb + c4;
#pragma unroll
        for (int j = 0; j < 4; j++) out[o + j] = tb[c4 + j][r];
    }
}

// ---------------- rmsnorm (fp16 out) ---------------------------------------
__global__ __launch_bounds__(256)
void rmsnorm_h(const float* __restrict__ x, const float* __restrict__ w,
               __half* __restrict__ o) {
    const int row = blockIdx.x;
    const float* xr = x + (size_t)row * DIM;
    float s = 0.f;
    for (int j = threadIdx.x; j < DIM; j += 256) { float v = xr[j]; s += v * v; }
    __shared__ float red[256];
    red[threadIdx.x] = s;
    __syncthreads();
    for (int st = 128; st > 0; st >>= 1) {
        if (threadIdx.x < st) red[threadIdx.x] += red[threadIdx.x + st];
        __syncthreads();
    }
    const float inv = rsqrtf(red[0] * (1.0f / DIM) + EPSV);
    __half* orow = o + (size_t)row * DIM;
    for (int j = threadIdx.x; j < DIM; j += 256)
        orow[j] = __float2half_rn(xr[j] * inv * w[j]);
}

// ---------------- RoPE -----------------------------------------------------
__global__ void init_invf_kernel() { g_invf[threadIdx.x] = pow(10000.0, -(double)threadIdx.x / 64.0); }
__global__ void rope_table_kernel() {
    int s = blockIdx.x, d = threadIdx.x;
    double ang = (double)s * g_invf[d];
    const double twopi = 6.283185307179586476925287;
    double r = ang - twopi * floor(ang / twopi + 0.5);
    float rf = (float)r;
    g_cs[s * 64 + d] = make_float2(cosf(rf), sinf(rf));
}
__global__ void rope_apply_h(__half* __restrict__ q, __half* __restrict__ k) {
    const int s = blockIdx.x, h = blockIdx.y, d = threadIdx.x;
    __half* base = (h < NH) ? (q + (size_t)s * (NH * HD) + h * HD)
                            : (k + (size_t)s * (NKV * HD) + (h - NH) * HD);
    float2 cs = g_cs[s * 64 + d];
    float x0 = __half2float(base[d]), x1 = __half2float(base[d + 64]);
    base[d]      = __float2half_rn(x0 * cs.x - x1 * cs.y);
    base[d + 64] = __float2half_rn(x1 * cs.x + x0 * cs.y);
}

// ---------------- softmax: fp32 scores -> fp16 probs (zero-pad to 128) -----
__global__ __launch_bounds__(256)
void softmax_kernel(const float* __restrict__ scores, __half* __restrict__ probs) {
    const int srow = blockIdx.x, h = blockIdx.y;
    const float* row = scores + ((size_t)h * SEQ + srow) * SEQ;
    __half* prow = probs + ((size_t)h * SEQ + srow) * SEQ;
    const int n = srow + 1;
    const int padn = ((n + 127) / 128) * 128;
    __shared__ float buf[SEQ];
    __shared__ float red[256];
    const int tid = threadIdx.x;
    float mx = -1e30f;
    for (int j = tid; j < n; j += 256) { float v = row[j]; buf[j] = v; mx = fmaxf(mx, v); }
    red[tid] = mx;
    __syncthreads();
    for (int st = 128; st > 0; st >>= 1) {
        if (tid < st) red[tid] = fmaxf(red[tid], red[tid + st]);
        __syncthreads();
    }
    mx = red[0];
    __syncthreads();
    float sum = 0.f;
    for (int j = tid; j < n; j += 256) { float e = fexp(buf[j] - mx); buf[j] = e; sum += e; }
    red[tid] = sum;
    __syncthreads();
    for (int st = 128; st > 0; st >>= 1) {
        if (tid < st) red[tid] += red[tid + st];
        __syncthreads();
    }
    const float inv = 1.0f / red[0];
    for (int j = tid; j < padn; j += 256)
        prow[j] = (j < n) ? __float2half_rn(buf[j] * inv) : __half(0.f);
}

// ---------------------------------------------------------------------------
// fp16 mma.sync GEMM (NT): C = A[M,K] @ B[N,K]^T, A,B __half K-major.
// BM=128, BN=128, BK=64, 256 threads (8 warps 2x4), warp tile 64x32.
// Tiles: 128 rows x 128B (64 halves), XOR-8 16B-chunk swizzle -> conflict-free
// ldmatrix and aligned cp.async. 3-stage ring, 1 barrier/k-tile.
// EPI: 0 fp16 plain, 1 fp32 +Aux, 2 fp32 *scale causal, 3 fp16 silu(Aux)*acc,
//      5 fp32 plain.
// ---------------------------------------------------------------------------
constexpr int TILEB = 128 * 128;          // bytes per A (or B) tile
constexpr int STGB  = 2 * TILEB;          // bytes per stage
constexpr int NSTAGE = 3;
constexpr int GEMM_SMEM = NSTAGE * STGB;  // 98304 B

template<int EPI, bool CAUSAL, bool CK>
__global__ __launch_bounds__(256, 2)
void mma_gemm(const __half* __restrict__ A, const __half* __restrict__ B,
              void* __restrict__ Cv, const float* __restrict__ Aux,
              int K, int lda, int ldb, int ldc,
              long zA, long zB, long zC, int bGroup, float scale) {
    const int row0 = blockIdx.y * 128;
    const int col0 = blockIdx.x * 128;
    if (CAUSAL && col0 > row0 + 127) return;
    const int bz = blockIdx.z;
    A += (size_t)bz * zA;
    B += (size_t)(bz / bGroup) * zB;
    if (EPI == 1 || EPI == 3) Aux += (size_t)bz * zC;

    extern __shared__ char smc[];
    const uint32_t smBase = smem_u32(smc);

    const int tid = threadIdx.x;
    const int wid = tid >> 5, lane = tid & 31;
    const int lr = lane >> 2, lc = lane & 3, l7 = lane & 7;
    const int wm = (wid & 1) * 64;
    const int wn = (wid >> 1) * 32;

    const int nkt = CK ? (row0 + 128) / 64 : K / 64;

    // fragment row/chunk selectors
    const int aRow = wm + ((lane >> 3) & 1) * 8 + l7;
    const int bRow = wn + ((lane >> 4) & 1) * 8 + l7;
    const int aSel = (lane >> 4) & 1;
    const int bSel = (lane >> 3) & 1;

    auto stage = [&](int s, int kt) {
        const uint32_t aB = smBase + (uint32_t)(s * STGB);
        const uint32_t bB = aB + (uint32_t)TILEB;
        const __half* Ap = A + (size_t)row0 * lda + kt * 64;
        const __half* Bp = B + (size_t)col0 * ldb + kt * 64;
#pragma unroll
        for (int j = 0; j < 4; j++) {
            int idx = j * 256 + tid, r = idx >> 3, c = idx & 7;
            uint32_t sw = (uint32_t)((c ^ (r & 7)) * 16);
            cp16(aB + (uint32_t)r * 128 + sw, Ap + (size_t)r * lda + c * 8);
            cp16(bB + (uint32_t)r * 128 + sw, Bp + (size_t)r * ldb + c * 8);
        }
    };

    float acc[4][4][4];
#pragma unroll
    for (int mt = 0; mt < 4; mt++)
#pragma unroll
        for (int nt = 0; nt < 4; nt++)
#pragma unroll
            for (int i = 0; i < 4; i++) acc[mt][nt][i] = 0.f;

    stage(0, 0);
    cp_commit();
    if (nkt > 1) { stage(1, 1); cp_commit(); }

    uint32_t af[2][4][4], bf[2][4][2];

    auto loadFrags = [&](int buf, int ks, uint32_t aB4, uint32_t bB4) {
        const uint32_t ca = (uint32_t)(((ks * 2 + aSel) ^ l7) * 16);
        const uint32_t cb = (uint32_t)(((ks * 2 + bSel) ^ l7) * 16);
#pragma unroll
        for (int mt = 0; mt < 4; mt++)
            ldsm_x4(af[buf][mt], aB4 + (uint32_t)(aRow + mt * 16) * 128 + ca);
#pragma unroll
        for (int ntp = 0; ntp < 2; ntp++) {
            uint32_t tmp[4];
            ldsm_x4(tmp, bB4 + (uint32_t)(bRow + ntp * 16) * 128 + cb);
            bf[buf][ntp * 2][0] = tmp[0]; bf[buf][ntp * 2][1] = tmp[1];
            bf[buf][ntp * 2 + 1][0] = tmp[2]; bf[buf][ntp * 2 + 1][1] = tmp[3];
        }
    };

    int s = 0;
    for (int kt = 0; kt < nkt; kt++) {
        if (kt == nkt - 1) cp_wait<0>(); else cp_wait<1>();
        __syncthreads();
        if (kt + 2 < nkt) {
            int s2 = s + 2; if (s2 >= NSTAGE) s2 -= NSTAGE;
            stage(s2, kt + 2);
            cp_commit();
        }

        const uint32_t aB4 = smBase + (uint32_t)(s * STGB);
        const uint32_t bB4 = aB4 + (uint32_t)TILEB;
        loadFrags(0, 0, aB4, bB4);
#pragma unroll
        for (int ks = 0; ks < 4; ks++) {
            if (ks < 3) loadFrags((ks + 1) & 1, ks + 1, aB4, bB4);
            const int cb = ks & 1;
#pragma unroll
            for (int mt = 0; mt < 4; mt++)
#pragma unroll
                for (int nt = 0; nt < 4; nt++)
                    mma_f16(acc[mt][nt], af[cb][mt], bf[cb][nt]);
        }
        if (++s >= NSTAGE) s -= NSTAGE;
    }

    // -------- epilogue
    __half* Ch = (__half*)Cv;
    float*  Cf = (float*)Cv;
    if (EPI == 0 || EPI == 3) Ch += (size_t)bz * zC;
    else                      Cf += (size_t)bz * zC;
#pragma unroll
    for (int mt = 0; mt < 4; mt++) {
        const int ra = row0 + wm + mt * 16 + lr;
        const int rb = ra + 8;
#pragma unroll
        for (int nt = 0; nt < 4; nt++) {
            const int c = col0 + wn + nt * 8 + lc * 2;
            float* a4 = acc[mt][nt];
            const size_t ia = (size_t)ra * ldc + c;
            const size_t ib = (size_t)rb * ldc + c;
            if (EPI == 0) {
                *(__half2*)&Ch[ia] = __floats2half2_rn(a4[0], a4[1]);
                *(__half2*)&Ch[ib] = __floats2half2_rn(a4[2], a4[3]);
            } else if (EPI == 1) {
                float2 xa = *(const float2*)&Aux[ia], xb = *(const float2*)&Aux[ib];
                *(float2*)&Cf[ia] = make_float2(a4[0] + xa.x, a4[1] + xa.y);
                *(float2*)&Cf[ib] = make_float2(a4[2] + xb.x, a4[3] + xb.y);
            } else if (EPI == 2) {
                if (c     <= ra) Cf[ia]     = a4[0] * scale;
                if (c + 1 <= ra) Cf[ia + 1] = a4[1] * scale;
                if (c     <= rb) Cf[ib]     = a4[2] * scale;
                if (c + 1 <= rb) Cf[ib + 1] = a4[3] * scale;
            } else if (EPI == 3) {
                float2 ga = *(const float2*)&Aux[ia], gb = *(const float2*)&Aux[ib];
                *(__half2*)&Ch[ia] = __floats2half2_rn(a4[0] * silu(ga.x), a4[1] * silu(ga.y));
                *(__half2*)&Ch[ib] = __floats2half2_rn(a4[2] * silu(gb.x), a4[3] * silu(gb.y));
            } else {  // EPI == 5
                *(float2*)&Cf[ia] = make_float2(a4[0], a4[1]);
                *(float2*)&Cf[ib] = make_float2(a4[2], a4[3]);
            }
        }
    }
}

// ---------------------------------------------------------------------------
extern "C" void kernel_launch(void* const* d_in, const int* in_sizes, int n_in,
                              void* d_out, int out_size) {
    (void)in_sizes; (void)n_in; (void)out_size;
    const float* x   = (const float*)d_in[0];
    const float* ln1 = (const float*)d_in[2];
    const float* Wq  = (const float*)d_in[3];
    const float* Wk  = (const float*)d_in[4];
    const float* Wv  = (const float*)d_in[5];
    const float* Wo  = (const float*)d_in[6];
    const float* ln2 = (const float*)d_in[7];
    const float* Wg  = (const float*)d_in[8];
    const float* Wu  = (const float*)d_in[9];
    const float* Wd  = (const float*)d_in[10];
    float* out = (float*)d_out;

    __half *h1h, *qh, *kh, *vh, *vTh, *ph, *ath, *h2h, *mmh;
    __half *WqTh, *WkTh, *WvTh, *WoTh, *WgTh, *WuTh, *WdTh;
    float *sc, *x2, *gg;
    cudaGetSymbolAddress((void**)&h1h, g_h1h); cudaGetSymbolAddress((void**)&qh, g_qh);
    cudaGetSymbolAddress((void**)&kh, g_kh);   cudaGetSymbolAddress((void**)&vh, g_vh);
    cudaGetSymbolAddress((void**)&vTh, g_vTh); cudaGetSymbolAddress((void**)&sc, g_sc);
    cudaGetSymbolAddress((void**)&ph, g_ph);   cudaGetSymbolAddress((void**)&ath, g_ath);
    cudaGetSymbolAddress((void**)&x2, g_x2);   cudaGetSymbolAddress((void**)&h2h, g_h2h);
    cudaGetSymbolAddress((void**)&gg, g_gg);   cudaGetSymbolAddress((void**)&mmh, g_mmh);
    cudaGetSymbolAddress((void**)&WqTh, g_WqTh); cudaGetSymbolAddress((void**)&WkTh, g_WkTh);
    cudaGetSymbolAddress((void**)&WvTh, g_WvTh); cudaGetSymbolAddress((void**)&WoTh, g_WoTh);
    cudaGetSymbolAddress((void**)&WgTh, g_WgTh); cudaGetSymbolAddress((void**)&WuTh, g_WuTh);
    cudaGetSymbolAddress((void**)&WdTh, g_WdTh);

    cudaFuncSetAttribute(mma_gemm<0, false, false>, cudaFuncAttributeMaxDynamicSharedMemorySize, GEMM_SMEM);
    cudaFuncSetAttribute(mma_gemm<0, false, true >, cudaFuncAttributeMaxDynamicSharedMemorySize, GEMM_SMEM);
    cudaFuncSetAttribute(mma_gemm<1, false, false>, cudaFuncAttributeMaxDynamicSharedMemorySize, GEMM_SMEM);
    cudaFuncSetAttribute(mma_gemm<2, true,  false>, cudaFuncAttributeMaxDynamicSharedMemorySize, GEMM_SMEM);
    cudaFuncSetAttribute(mma_gemm<3, false, false>, cudaFuncAttributeMaxDynamicSharedMemorySize, GEMM_SMEM);
    cudaFuncSetAttribute(mma_gemm<5, false, false>, cudaFuncAttributeMaxDynamicSharedMemorySize, GEMM_SMEM);

    const float iscale = 0.08838834764831843f;  // 1/sqrt(128)

    // weight transposes -> fp16 (halved write traffic)
    transpose_wh<<<dim3(DIM / 64, DIM / 64), 256>>>(Wq, WqTh, DIM, DIM);
    transpose_wh<<<dim3(512 / 64, DIM / 64), 256>>>(Wk, WkTh, DIM, 512);
    transpose_wh<<<dim3(512 / 64, DIM / 64), 256>>>(Wv, WvTh, DIM, 512);
    transpose_wh<<<dim3(DIM / 64, DIM / 64), 256>>>(Wo, WoTh, DIM, DIM);
    transpose_wh<<<dim3(FF / 64, DIM / 64), 256>>>(Wg, WgTh, DIM, FF);
    transpose_wh<<<dim3(FF / 64, DIM / 64), 256>>>(Wu, WuTh, DIM, FF);
    transpose_wh<<<dim3(DIM / 64, FF / 64), 256>>>(Wd, WdTh, FF, DIM);
    init_invf_kernel<<<1, 64>>>();
    rope_table_kernel<<<SEQ, 64>>>();

    rmsnorm_h<<<SEQ, 256>>>(x, ln1, h1h);

    // projections (fp16 out)
    mma_gemm<0, false, false><<<dim3(16, 16, 1), 256, GEMM_SMEM>>>(
        h1h, WqTh, qh, nullptr, DIM, DIM, DIM, DIM, 0, 0, 0, 1, 0.f);
    mma_gemm<0, false, false><<<dim3(4, 16, 1), 256, GEMM_SMEM>>>(
        h1h, WkTh, kh, nullptr, DIM, DIM, DIM, 512, 0, 0, 0, 1, 0.f);
    mma_gemm<0, false, false><<<dim3(4, 16, 1), 256, GEMM_SMEM>>>(
        h1h, WvTh, vh, nullptr, DIM, DIM, DIM, 512, 0, 0, 0, 1, 0.f);
    transpose_hh<<<dim3(512 / 64, SEQ / 64), 256>>>(vh, vTh, SEQ, 512);

    rope_apply_h<<<dim3(SEQ, NH + NKV), 64>>>(qh, kh);

    // scores = causal(q @ k^T) * iscale  -> fp32
    mma_gemm<2, true, false><<<dim3(16, 16, NH), 256, GEMM_SMEM>>>(
        qh, kh, sc, nullptr, HD, DIM, 512, SEQ,
        HD, HD, (long)SEQ * SEQ, NKV, iscale);

    softmax_kernel<<<dim3(SEQ, NH), 256>>>(sc, ph);

    // at = probs @ v  (fp16, causal K-limit)
    mma_gemm<0, false, true><<<dim3(1, 16, NH), 256, GEMM_SMEM>>>(
        ph, vTh, ath, nullptr, SEQ, SEQ, SEQ, DIM,
        (long)SEQ * SEQ, (long)HD * SEQ, HD, NKV, 0.f);

    // x2 = at @ Wo + x   (fp32)
    mma_gemm<1, false, false><<<dim3(16, 16, 1), 256, GEMM_SMEM>>>(
        ath, WoTh, x2, x, DIM, DIM, DIM, DIM, 0, 0, 0, 1, 0.f);

    rmsnorm_h<<<SEQ, 256>>>(x2, ln2, h2h);

    // MLP: gg fp32; mm = fp16(silu(gg)*(h2@Wu)); out = mm@Wd + x2
    mma_gemm<5, false, false><<<dim3(64, 16, 1), 256, GEMM_SMEM>>>(
        h2h, WgTh, gg, nullptr, DIM, DIM, DIM, FF, 0, 0, 0, 1, 0.f);
    mma_gemm<3, false, false><<<dim3(64, 16, 1), 256, GEMM_SMEM>>>(
        h2h, WuTh, mmh, gg, DIM, DIM, DIM, FF, 0, 0, 0, 1, 0.f);
    mma_gemm<1, false, false><<<dim3(16, 16, 1), 256, GEMM_SMEM>>>(
        mmh, WdTh, out, x2, FF, FF, FF, DIM, 0, 0, 0, 1, 0.f);
}

// round 13
// speedup vs baseline: 2.0230x; 1.0464x over previous
#include <cuda_runtime.h>
#include <cuda_fp16.h>
#include <cstdint>
#include <math.h>

constexpr int SEQ = 2048, DIM = 2048, NH = 16, NKV = 4, HD = 128, FF = 8192;
constexpr int QKVN = NH * HD + 2 * NKV * HD;   // 3072
constexpr float EPSV = 1e-6f;

// ---------------------------------------------------------------------------
// Scratch (device globals — allocation forbidden)
// ---------------------------------------------------------------------------
__device__ __half g_h1h [SEQ * DIM];
__device__ __half g_qkvh[SEQ * QKVN];            // q | k | v packed per row
__device__ __half g_vTh [NKV * HD * SEQ];
__device__ float  g_sc  [(long)NH * SEQ * SEQ];  // fp32 scores
__device__ __half g_ph  [(long)NH * SEQ * SEQ];  // fp16 probs
__device__ __half g_ath [SEQ * NH * HD];
__device__ float  g_x2  [SEQ * DIM];
__device__ __half g_h2h [SEQ * DIM];
__device__ __half g_mmh [(long)SEQ * FF];
__device__ __half g_Wqkvh[(long)QKVN * DIM];
__device__ __half g_WoTh[DIM * DIM];
__device__ __half g_WgTh[(long)FF * DIM];
__device__ __half g_WuTh[(long)FF * DIM];
__device__ __half g_WdTh[(long)DIM * FF];
__device__ double g_invf[64];
__device__ float2 g_cs[SEQ * 64];

// ---------------------------------------------------------------------------
__device__ __forceinline__ uint32_t smem_u32(const void* p) {
    uint32_t a;
    asm("{ .reg .u64 t; cvta.to.shared.u64 t, %1; cvt.u32.u64 %0, t; }" : "=r"(a) : "l"(p));
    return a;
}
__device__ __forceinline__ void cp16(uint32_t dst, const void* src) {
    asm volatile("cp.async.cg.shared.global [%0], [%1], 16;" :: "r"(dst), "l"(src) : "memory");
}
__device__ __forceinline__ void cp_commit() {
    asm volatile("cp.async.commit_group;" ::: "memory");
}
template<int N> __device__ __forceinline__ void cp_wait() {
    asm volatile("cp.async.wait_group %0;" :: "n"(N) : "memory");
}
__device__ __forceinline__ void mma_f16(float* c, const uint32_t* a, const uint32_t* b) {
    asm volatile(
        "mma.sync.aligned.m16n8k16.row.col.f32.f16.f16.f32 "
        "{%0,%1,%2,%3}, {%4,%5,%6,%7}, {%8,%9}, {%0,%1,%2,%3};"
        : "+f"(c[0]), "+f"(c[1]), "+f"(c[2]), "+f"(c[3])
        : "r"(a[0]), "r"(a[1]), "r"(a[2]), "r"(a[3]), "r"(b[0]), "r"(b[1]));
}
__device__ __forceinline__ void ldsm_x4(uint32_t* r, uint32_t addr) {
    asm volatile("ldmatrix.sync.aligned.m8n8.x4.shared.b16 {%0,%1,%2,%3}, [%4];"
                 : "=r"(r[0]), "=r"(r[1]), "=r"(r[2]), "=r"(r[3]) : "r"(addr));
}

__device__ __forceinline__ float fexp(float x) {  // accurate for x <= 0
    float t = x * 1.4426950408889634f;
    float r = rintf(t), f = t - r;
    int i = (int)r;
    float p = 0.0013333558f;
    p = fmaf(p, f, 0.0096181291f);
    p = fmaf(p, f, 0.0555041087f);
    p = fmaf(p, f, 0.2402264476f);
    p = fmaf(p, f, 0.6931471806f);
    p = fmaf(p, f, 1.0f);
    float s = __int_as_float((i + 127) << 23);
    return (x < -80.f) ? 0.f : p * s;
}
__device__ __forceinline__ float silu(float g) {
    float t = fexp(-fabsf(g));
    float s = (g >= 0.f) ? 1.f / (1.f + t) : t / (1.f + t);
    return g * s;
}

// ---------------- weight transpose fp32 -> fp16: out[C,R] (R10-proven) -----
__global__ __launch_bounds__(256)
void transpose_wh(const float* __restrict__ in, __half* __restrict__ out, int R, int C) {
    __shared__ float tb[64][65];
    const int rb = blockIdx.y * 64, cb = blockIdx.x * 64;
    const int tr = threadIdx.x >> 4;
    const int c4 = (threadIdx.x & 15) * 4;
#pragma unroll
    for (int i = 0; i < 4; i++) {
        int r = tr + i * 16;
        float4 v = *(const float4*)&in[(size_t)(rb + r) * C + cb + c4];
        tb[r][c4 + 0] = v.x; tb[r][c4 + 1] = v.y;
        tb[r][c4 + 2] = v.z; tb[r][c4 + 3] = v.w;
    }
    __syncthreads();
#pragma unroll
    for (int i = 0; i < 4; i++) {
        int r = tr + i * 16;
        size_t o = (size_t)(cb + r) * R + rb + c4;
        *(__half2*)&out[o]     = __floats2half2_rn(tb[c4 + 0][r], tb[c4 + 1][r]);
        *(__half2*)&out[o + 2] = __floats2half2_rn(tb[c4 + 2][r], tb[c4 + 3][r]);
    }
}

// half -> half transpose (for v view inside qkv), scalar, ldin-strided input
__global__ __launch_bounds__(256)
void transpose_hh(const __half* __restrict__ in, __half* __restrict__ out,
                  int R, int C, int ldin) {
    __shared__ __half tb[64][65];
    const int rb = blockIdx.y * 64, cb = blockIdx.x * 64;
    const int tr = threadIdx.x >> 4;
    const int c4 = (threadIdx.x & 15) * 4;
#pragma unroll
    for (int i = 0; i < 4; i++) {
        int r = tr + i * 16;
#pragma unroll
        for (int j = 0; j < 4; j++)
            tb[r][c4 + j] = in[(size_t)(rb + r) * ldin + cb + c4 + j];
    }
    __syncthreads();
#pragma unroll
    for (int i = 0; i < 4; i++) {
        int r = tr + i * 16;
        size_t o = (size_t)(cb + r) * R + rb + c4;
#pragma unroll
        for (int j = 0; j < 4; j++) out[o + j] = tb[c4 + j][r];
    }
}

// ---------------- rmsnorm (fp16 out) ---------------------------------------
__global__ __launch_bounds__(256)
void rmsnorm_h(const float* __restrict__ x, const float* __restrict__ w,
               __half* __restrict__ o) {
    const int row = blockIdx.x;
    const float* xr = x + (size_t)row * DIM;
    float s = 0.f;
    for (int j = threadIdx.x; j < DIM; j += 256) { float v = xr[j]; s += v * v; }
    __shared__ float red[256];
    red[threadIdx.x] = s;
    __syncthreads();
    for (int st = 128; st > 0; st >>= 1) {
        if (threadIdx.x < st) red[threadIdx.x] += red[threadIdx.x + st];
        __syncthreads();
    }
    const float inv = rsqrtf(red[0] * (1.0f / DIM) + EPSV);
    __half* orow = o + (size_t)row * DIM;
    for (int j = threadIdx.x; j < DIM; j += 256)
        orow[j] = __float2half_rn(xr[j] * inv * w[j]);
}

// ---------------- RoPE -----------------------------------------------------
__global__ void init_invf_kernel() { g_invf[threadIdx.x] = pow(10000.0, -(double)threadIdx.x / 64.0); }
__global__ void rope_table_kernel() {
    int s = blockIdx.x, d = threadIdx.x;
    double ang = (double)s * g_invf[d];
    const double twopi = 6.283185307179586476925287;
    double r = ang - twopi * floor(ang / twopi + 0.5);
    float rf = (float)r;
    g_cs[s * 64 + d] = make_float2(cosf(rf), sinf(rf));
}
// q heads at cols [0,2048), k heads at cols [2048,2560) of qkv (stride QKVN)
__global__ void rope_apply_h(__half* __restrict__ qkv) {
    const int s = blockIdx.x, h = blockIdx.y, d = threadIdx.x;
    __half* base = qkv + (size_t)s * QKVN +
                   ((h < NH) ? h * HD : (NH * HD + (h - NH) * HD));
    float2 cs = g_cs[s * 64 + d];
    float x0 = __half2float(base[d]), x1 = __half2float(base[d + 64]);
    base[d]      = __float2half_rn(x0 * cs.x - x1 * cs.y);
    base[d + 64] = __float2half_rn(x1 * cs.x + x0 * cs.y);
}

// ---------------- softmax: fp32 scores -> fp16 probs (zero-pad to 128) -----
__global__ __launch_bounds__(256)
void softmax_kernel(const float* __restrict__ scores, __half* __restrict__ probs) {
    const int srow = blockIdx.x, h = blockIdx.y;
    const float* row = scores + ((size_t)h * SEQ + srow) * SEQ;
    __half* prow = probs + ((size_t)h * SEQ + srow) * SEQ;
    const int n = srow + 1;
    const int padn = ((n + 127) / 128) * 128;
    __shared__ float buf[SEQ];
    __shared__ float red[256];
    const int tid = threadIdx.x;
    float mx = -1e30f;
    for (int j = tid; j < n; j += 256) { float v = row[j]; buf[j] = v; mx = fmaxf(mx, v); }
    red[tid] = mx;
    __syncthreads();
    for (int st = 128; st > 0; st >>= 1) {
        if (tid < st) red[tid] = fmaxf(red[tid], red[tid + st]);
        __syncthreads();
    }
    mx = red[0];
    __syncthreads();
    float sum = 0.f;
    for (int j = tid; j < n; j += 256) { float e = fexp(buf[j] - mx); buf[j] = e; sum += e; }
    red[tid] = sum;
    __syncthreads();
    for (int st = 128; st > 0; st >>= 1) {
        if (tid < st) red[tid] += red[tid + st];
        __syncthreads();
    }
    const float inv = 1.0f / red[0];
    for (int j = tid; j < padn; j += 256)
        prow[j] = (j < n) ? __float2half_rn(buf[j] * inv) : __half(0.f);
}

// ---------------------------------------------------------------------------
// fp16 mma.sync GEMM (NT): C = A[M,K] @ B[N,K]^T, __half operands K-major.
// BM=128, BN=128, BK=64, 256 threads (8 warps 2x4), warp tile 64x32.
// XOR-8 16B-chunk swizzle. 3-stage cp.async ring, 1 barrier/k-tile.
// EPI: 0 fp16 plain, 1 fp32 +Aux, 2 fp32 *scale causal.
// ---------------------------------------------------------------------------
constexpr int TILEB = 128 * 128;          // bytes per 128-row tile
constexpr int STGB  = 2 * TILEB;
constexpr int NSTAGE = 3;
constexpr int GEMM_SMEM = NSTAGE * STGB;  // 98304 B

template<int EPI, bool CAUSAL, bool CK>
__global__ __launch_bounds__(256, 2)
void mma_gemm(const __half* __restrict__ A, const __half* __restrict__ B,
              void* __restrict__ Cv, const float* __restrict__ Aux,
              int K, int lda, int ldb, int ldc,
              long zA, long zB, long zC, int bGroup, float scale) {
    const int row0 = blockIdx.y * 128;
    const int col0 = blockIdx.x * 128;
    if (CAUSAL && col0 > row0 + 127) return;
    const int bz = blockIdx.z;
    A += (size_t)bz * zA;
    B += (size_t)(bz / bGroup) * zB;
    if (EPI == 1) Aux += (size_t)bz * zC;

    extern __shared__ char smc[];
    const uint32_t smBase = smem_u32(smc);

    const int tid = threadIdx.x;
    const int wid = tid >> 5, lane = tid & 31;
    const int lr = lane >> 2, lc = lane & 3, l7 = lane & 7;
    const int wm = (wid & 1) * 64;
    const int wn = (wid >> 1) * 32;

    const int nkt = CK ? (row0 + 128) / 64 : K / 64;

    const int aRow = wm + ((lane >> 3) & 1) * 8 + l7;
    const int bRow = wn + ((lane >> 4) & 1) * 8 + l7;
    const int aSel = (lane >> 4) & 1;
    const int bSel = (lane >> 3) & 1;

    auto stage = [&](int s, int kt) {
        const uint32_t aB = smBase + (uint32_t)(s * STGB);
        const uint32_t bB = aB + (uint32_t)TILEB;
        const __half* Ap = A + (size_t)row0 * lda + kt * 64;
        const __half* Bp = B + (size_t)col0 * ldb + kt * 64;
#pragma unroll
        for (int j = 0; j < 4; j++) {
            int idx = j * 256 + tid, r = idx >> 3, c = idx & 7;
            uint32_t sw = (uint32_t)((c ^ (r & 7)) * 16);
            cp16(aB + (uint32_t)r * 128 + sw, Ap + (size_t)r * lda + c * 8);
            cp16(bB + (uint32_t)r * 128 + sw, Bp + (size_t)r * ldb + c * 8);
        }
    };

    float acc[4][4][4];
#pragma unroll
    for (int mt = 0; mt < 4; mt++)
#pragma unroll
        for (int nt = 0; nt < 4; nt++)
#pragma unroll
            for (int i = 0; i < 4; i++) acc[mt][nt][i] = 0.f;

    stage(0, 0);
    cp_commit();
    if (nkt > 1) { stage(1, 1); cp_commit(); }

    uint32_t af[2][4][4], bf[2][4][2];

    auto loadFrags = [&](int buf, int ks, uint32_t aB4, uint32_t bB4) {
        const uint32_t ca = (uint32_t)(((ks * 2 + aSel) ^ l7) * 16);
        const uint32_t cb = (uint32_t)(((ks * 2 + bSel) ^ l7) * 16);
#pragma unroll
        for (int mt = 0; mt < 4; mt++)
            ldsm_x4(af[buf][mt], aB4 + (uint32_t)(aRow + mt * 16) * 128 + ca);
#pragma unroll
        for (int ntp = 0; ntp < 2; ntp++) {
            uint32_t tmp[4];
            ldsm_x4(tmp, bB4 + (uint32_t)(bRow + ntp * 16) * 128 + cb);
            bf[buf][ntp * 2][0] = tmp[0]; bf[buf][ntp * 2][1] = tmp[1];
            bf[buf][ntp * 2 + 1][0] = tmp[2]; bf[buf][ntp * 2 + 1][1] = tmp[3];
        }
    };

    int s = 0;
    for (int kt = 0; kt < nkt; kt++) {
        if (kt == nkt - 1) cp_wait<0>(); else cp_wait<1>();
        __syncthreads();
        if (kt + 2 < nkt) {
            int s2 = s + 2; if (s2 >= NSTAGE) s2 -= NSTAGE;
            stage(s2, kt + 2);
            cp_commit();
        }
        const uint32_t aB4 = smBase + (uint32_t)(s * STGB);
        const uint32_t bB4 = aB4 + (uint32_t)TILEB;
        loadFrags(0, 0, aB4, bB4);
#pragma unroll
        for (int ks = 0; ks < 4; ks++) {
            if (ks < 3) loadFrags((ks + 1) & 1, ks + 1, aB4, bB4);
            const int cb = ks & 1;
#pragma unroll
            for (int mt = 0; mt < 4; mt++)
#pragma unroll
                for (int nt = 0; nt < 4; nt++)
                    mma_f16(acc[mt][nt], af[cb][mt], bf[cb][nt]);
        }
        if (++s >= NSTAGE) s -= NSTAGE;
    }

    __half* Ch = (__half*)Cv;
    float*  Cf = (float*)Cv;
    if (EPI == 0) Ch += (size_t)bz * zC;
    else          Cf += (size_t)bz * zC;
#pragma unroll
    for (int mt = 0; mt < 4; mt++) {
        const int ra = row0 + wm + mt * 16 + lr;
        const int rb = ra + 8;
#pragma unroll
        for (int nt = 0; nt < 4; nt++) {
            const int c = col0 + wn + nt * 8 + lc * 2;
            float* a4 = acc[mt][nt];
            const size_t ia = (size_t)ra * ldc + c;
            const size_t ib = (size_t)rb * ldc + c;
            if (EPI == 0) {
                *(__half2*)&Ch[ia] = __floats2half2_rn(a4[0], a4[1]);
                *(__half2*)&Ch[ib] = __floats2half2_rn(a4[2], a4[3]);
            } else if (EPI == 1) {
                float2 xa = *(const float2*)&Aux[ia], xb = *(const float2*)&Aux[ib];
                *(float2*)&Cf[ia] = make_float2(a4[0] + xa.x, a4[1] + xa.y);
                *(float2*)&Cf[ib] = make_float2(a4[2] + xb.x, a4[3] + xb.y);
            } else {  // EPI == 2
                if (c     <= ra) Cf[ia]     = a4[0] * scale;
                if (c + 1 <= ra) Cf[ia + 1] = a4[1] * scale;
                if (c     <= rb) Cf[ib]     = a4[2] * scale;
                if (c + 1 <= rb) Cf[ib + 1] = a4[3] * scale;
            }
        }
    }
}

// ---------------------------------------------------------------------------
// Fused gate+up MLP: per CTA, 128 rows x 64 ff-cols.
// Warps 0-3 compute gate = h2 @ Wg^T; warps 4-7 compute up = h2 @ Wu^T.
// Epilogue: gate fp32 via smem -> C = half(silu(g) * u). One A stage shared.
// Stage: A 16KB + Bg 8KB + Bu 8KB = 32KB; 3 stages = 96KB.
// ---------------------------------------------------------------------------
__global__ __launch_bounds__(256, 2)
void mma_mlp(const __half* __restrict__ A, const __half* __restrict__ Bg,
             const __half* __restrict__ Bu, __half* __restrict__ C) {
    const int row0 = blockIdx.y * 128;
    const int ffc0 = blockIdx.x * 64;

    extern __shared__ char smc[];
    const uint32_t smBase = smem_u32(smc);

    const int tid = threadIdx.x;
    const int wid = tid >> 5, lane = tid & 31;
    const int lr = lane >> 2, lc = lane & 3, l7 = lane & 7;
    const int role = wid >> 2;            // 0 = gate, 1 = up
    const int w2 = wid & 3;
    const int wm = (w2 & 1) * 64;
    const int wn = (w2 >> 1) * 32;

    const int aRow = wm + ((lane >> 3) & 1) * 8 + l7;
    const int bRow = wn + ((lane >> 4) & 1) * 8 + l7;
    const int aSel = (lane >> 4) & 1;
    const int bSel = (lane >> 3) & 1;

    constexpr int nkt = DIM / 64;   // 32

    auto stage = [&](int s, int kt) {
        const uint32_t aB = smBase + (uint32_t)(s * STGB);
        const uint32_t gB = aB + 16384u;
        const uint32_t uB = aB + 24576u;
        const __half* Ap = A + (size_t)row0 * DIM + kt * 64;
        const __half* Gp = Bg + (size_t)ffc0 * DIM + kt * 64;
        const __half* Up = Bu + (size_t)ffc0 * DIM + kt * 64;
#pragma unroll
        for (int j = 0; j < 4; j++) {
            int idx = j * 256 + tid, r = idx >> 3, c = idx & 7;
            uint32_t sw = (uint32_t)((c ^ (r & 7)) * 16);
            cp16(aB + (uint32_t)r * 128 + sw, Ap + (size_t)r * DIM + c * 8);
        }
#pragma unroll
        for (int j = 0; j < 2; j++) {
            int idx = j * 256 + tid, r = idx >> 3, c = idx & 7;  // r 0..63
            uint32_t sw = (uint32_t)((c ^ (r & 7)) * 16);
            cp16(gB + (uint32_t)r * 128 + sw, Gp + (size_t)r * DIM + c * 8);
            cp16(uB + (uint32_t)r * 128 + sw, Up + (size_t)r * DIM + c * 8);
        }
    };

    float acc[4][4][4];
#pragma unroll
    for (int mt = 0; mt < 4; mt++)
#pragma unroll
        for (int nt = 0; nt < 4; nt++)
#pragma unroll
            for (int i = 0; i < 4; i++) acc[mt][nt][i] = 0.f;

    stage(0, 0);
    cp_commit();
    stage(1, 1);
    cp_commit();

    uint32_t af[2][4][4], bf[2][4][2];
    const uint32_t bOff = 16384u + (role ? 8192u : 0u);

    auto loadFrags = [&](int buf, int ks, uint32_t aB4, uint32_t bB4) {
        const uint32_t ca = (uint32_t)(((ks * 2 + aSel) ^ l7) * 16);
        const uint32_t cb = (uint32_t)(((ks * 2 + bSel) ^ l7) * 16);
#pragma unroll
        for (int mt = 0; mt < 4; mt++)
            ldsm_x4(af[buf][mt], aB4 + (uint32_t)(aRow + mt * 16) * 128 + ca);
#pragma unroll
        for (int ntp = 0; ntp < 2; ntp++) {
            uint32_t tmp[4];
            ldsm_x4(tmp, bB4 + (uint32_t)(bRow + ntp * 16) * 128 + cb);
            bf[buf][ntp * 2][0] = tmp[0]; bf[buf][ntp * 2][1] = tmp[1];
            bf[buf][ntp * 2 + 1][0] = tmp[2]; bf[buf][ntp * 2 + 1][1] = tmp[3];
        }
    };

    int s = 0;
    for (int kt = 0; kt < nkt; kt++) {
        if (kt == nkt - 1) cp_wait<0>(); else cp_wait<1>();
        __syncthreads();
        if (kt + 2 < nkt) {
            int s2 = s + 2; if (s2 >= NSTAGE) s2 -= NSTAGE;
            stage(s2, kt + 2);
            cp_commit();
        }
        const uint32_t aB4 = smBase + (uint32_t)(s * STGB);
        const uint32_t bB4 = aB4 + bOff;
        loadFrags(0, 0, aB4, bB4);
#pragma unroll
        for (int ks = 0; ks < 4; ks++) {
            if (ks < 3) loadFrags((ks + 1) & 1, ks + 1, aB4, bB4);
            const int cb = ks & 1;
#pragma unroll
            for (int mt = 0; mt < 4; mt++)
#pragma unroll
                for (int nt = 0; nt < 4; nt++)
                    mma_f16(acc[mt][nt], af[cb][mt], bf[cb][nt]);
        }
        if (++s >= NSTAGE) s -= NSTAGE;
    }

    // epilogue: gate -> smem (fp32), then up warps combine + store fp16
    __syncthreads();
    float* gsm = (float*)smc;   // 128 x 66 fp32 = 33792 B
    if (role == 0) {
#pragma unroll
        for (int mt = 0; mt < 4; mt++) {
            const int ra = wm + mt * 16 + lr, rb = ra + 8;
#pragma unroll
            for (int nt = 0; nt < 4; nt++) {
                const int cl = wn + nt * 8 + lc * 2;
                float* a4 = acc[mt][nt];
                gsm[ra * 66 + cl] = a4[0]; gsm[ra * 66 + cl + 1] = a4[1];
                gsm[rb * 66 + cl] = a4[2]; gsm[rb * 66 + cl + 1] = a4[3];
            }
        }
    }
    __syncthreads();
    if (role == 1) {
#pragma unroll
        for (int mt = 0; mt < 4; mt++) {
            const int ra = wm + mt * 16 + lr, rb = ra + 8;
#pragma unroll
            for (int nt = 0; nt < 4; nt++) {
                const int cl = wn + nt * 8 + lc * 2;
                float* a4 = acc[mt][nt];
                float g0 = gsm[ra * 66 + cl], g1 = gsm[ra * 66 + cl + 1];
                float g2 = gsm[rb * 66 + cl], g3 = gsm[rb * 66 + cl + 1];
                size_t ia = (size_t)(row0 + ra) * FF + ffc0 + cl;
                size_t ib = (size_t)(row0 + rb) * FF + ffc0 + cl;
                *(__half2*)&C[ia] = __floats2half2_rn(silu(g0) * a4[0], silu(g1) * a4[1]);
                *(__half2*)&C[ib] = __floats2half2_rn(silu(g2) * a4[2], silu(g3) * a4[3]);
            }
        }
    }
}

// ---------------------------------------------------------------------------
extern "C" void kernel_launch(void* const* d_in, const int* in_sizes, int n_in,
                              void* d_out, int out_size) {
    (void)in_sizes; (void)n_in; (void)out_size;
    const float* x   = (const float*)d_in[0];
    const float* ln1 = (const float*)d_in[2];
    const float* Wq  = (const float*)d_in[3];
    const float* Wk  = (const float*)d_in[4];
    const float* Wv  = (const float*)d_in[5];
    const float* Wo  = (const float*)d_in[6];
    const float* ln2 = (const float*)d_in[7];
    const float* Wg  = (const float*)d_in[8];
    const float* Wu  = (const float*)d_in[9];
    const float* Wd  = (const float*)d_in[10];
    float* out = (float*)d_out;

    __half *h1h, *qkvh, *vTh, *ph, *ath, *h2h, *mmh;
    __half *Wqkvh, *WoTh, *WgTh, *WuTh, *WdTh;
    float *sc, *x2;
    cudaGetSymbolAddress((void**)&h1h, g_h1h);   cudaGetSymbolAddress((void**)&qkvh, g_qkvh);
    cudaGetSymbolAddress((void**)&vTh, g_vTh);   cudaGetSymbolAddress((void**)&sc, g_sc);
    cudaGetSymbolAddress((void**)&ph, g_ph);     cudaGetSymbolAddress((void**)&ath, g_ath);
    cudaGetSymbolAddress((void**)&x2, g_x2);     cudaGetSymbolAddress((void**)&h2h, g_h2h);
    cudaGetSymbolAddress((void**)&mmh, g_mmh);
    cudaGetSymbolAddress((void**)&Wqkvh, g_Wqkvh); cudaGetSymbolAddress((void**)&WoTh, g_WoTh);
    cudaGetSymbolAddress((void**)&WgTh, g_WgTh);   cudaGetSymbolAddress((void**)&WuTh, g_WuTh);
    cudaGetSymbolAddress((void**)&WdTh, g_WdTh);

    cudaFuncSetAttribute(mma_gemm<0, false, false>, cudaFuncAttributeMaxDynamicSharedMemorySize, GEMM_SMEM);
    cudaFuncSetAttribute(mma_gemm<0, false, true >, cudaFuncAttributeMaxDynamicSharedMemorySize, GEMM_SMEM);
    cudaFuncSetAttribute(mma_gemm<1, false, false>, cudaFuncAttributeMaxDynamicSharedMemorySize, GEMM_SMEM);
    cudaFuncSetAttribute(mma_gemm<2, true,  false>, cudaFuncAttributeMaxDynamicSharedMemorySize, GEMM_SMEM);
    cudaFuncSetAttribute(mma_mlp, cudaFuncAttributeMaxDynamicSharedMemorySize, GEMM_SMEM);

    const float iscale = 0.08838834764831843f;  // 1/sqrt(128)

    // weight transposes -> fp16 (QKV packed into one buffer, R10-proven kernel)
    transpose_wh<<<dim3(DIM / 64, DIM / 64), 256>>>(Wq, Wqkvh, DIM, DIM);
    transpose_wh<<<dim3(512 / 64, DIM / 64), 256>>>(Wk, Wqkvh + (size_t)2048 * DIM, DIM, 512);
    transpose_wh<<<dim3(512 / 64, DIM / 64), 256>>>(Wv, Wqkvh + (size_t)2560 * DIM, DIM, 512);
    transpose_wh<<<dim3(DIM / 64, DIM / 64), 256>>>(Wo, WoTh, DIM, DIM);
    transpose_wh<<<dim3(FF / 64, DIM / 64), 256>>>(Wg, WgTh, DIM, FF);
    transpose_wh<<<dim3(FF / 64, DIM / 64), 256>>>(Wu, WuTh, DIM, FF);
    transpose_wh<<<dim3(DIM / 64, FF / 64), 256>>>(Wd, WdTh, FF, DIM);
    init_invf_kernel<<<1, 64>>>();
    rope_table_kernel<<<SEQ, 64>>>();

    rmsnorm_h<<<SEQ, 256>>>(x, ln1, h1h);

    // fused QKV projection: qkv[S][3072]
    mma_gemm<0, false, false><<<dim3(QKVN / 128, 16, 1), 256, GEMM_SMEM>>>(
        h1h, Wqkvh, qkvh, nullptr, DIM, DIM, DIM, QKVN, 0, 0, 0, 1, 0.f);

    // vT from v view (cols 2560.. of qkv)
    transpose_hh<<<dim3(512 / 64, SEQ / 64), 256>>>(
        qkvh + NH * HD + NKV * HD, vTh, SEQ, NKV * HD, QKVN);

    rope_apply_h<<<dim3(SEQ, NH + NKV), 64>>>(qkvh);

    // scores = causal(q @ k^T) * iscale  -> fp32
    mma_gemm<2, true, false><<<dim3(16, 16, NH), 256, GEMM_SMEM>>>(
        qkvh, qkvh + NH * HD, sc, nullptr, HD, QKVN, QKVN, SEQ,
        HD, HD, (long)SEQ * SEQ, NKV, iscale);

    softmax_kernel<<<dim3(SEQ, NH), 256>>>(sc, ph);

    // at = probs @ v (fp16, causal K-limit)
    mma_gemm<0, false, true><<<dim3(1, 16, NH), 256, GEMM_SMEM>>>(
        ph, vTh, ath, nullptr, SEQ, SEQ, SEQ, DIM,
        (long)SEQ * SEQ, (long)HD * SEQ, HD, NKV, 0.f);

    // x2 = at @ Wo + x (fp32)
    mma_gemm<1, false, false><<<dim3(16, 16, 1), 256, GEMM_SMEM>>>(
        ath, WoTh, x2, x, DIM, DIM, DIM, DIM, 0, 0, 0, 1, 0.f);

    rmsnorm_h<<<SEQ, 256>>>(x2, ln2, h2h);

    // fused gate+up MLP: mm = half(silu(h2@Wg) * (h2@Wu))
    mma_mlp<<<dim3(FF / 64, 16, 1), 256, GEMM_SMEM>>>(h2h, WgTh, WuTh, mmh);

    // out = mm @ Wd + x2 (fp32)
    mma_gemm<1, false, false><<<dim3(16, 16, 1), 256, GEMM_SMEM>>>(
        mmh, WdTh, out, x2, FF, FF, FF, DIM, 0, 0, 0, 1, 0.f);
}

// round 14
// speedup vs baseline: 2.1868x; 1.0809x over previous
#include <cuda_runtime.h>
#include <cuda_fp16.h>
#include <cstdint>
#include <math.h>

constexpr int SEQ = 2048, DIM = 2048, NH = 16, NKV = 4, HD = 128, FF = 8192;
constexpr int QKVN = NH * HD + 2 * NKV * HD;   // 3072
constexpr float EPSV = 1e-6f;

// ---------------------------------------------------------------------------
// Scratch (device globals — allocation forbidden)
// ---------------------------------------------------------------------------
__device__ __half g_h1h [SEQ * DIM];
__device__ __half g_qkvh[SEQ * QKVN];            // q | k | v packed per row
__device__ __half g_ath [SEQ * NH * HD];
__device__ float  g_x2  [SEQ * DIM];
__device__ __half g_h2h [SEQ * DIM];
__device__ __half g_mmh [(long)SEQ * FF];
__device__ __half g_Wqkvh[(long)QKVN * DIM];
__device__ __half g_WoTh[DIM * DIM];
__device__ __half g_WgTh[(long)FF * DIM];
__device__ __half g_WuTh[(long)FF * DIM];
__device__ __half g_WdTh[(long)DIM * FF];
__device__ double g_invf[64];
__device__ float2 g_cs[SEQ * 64];

// ---------------------------------------------------------------------------
__device__ __forceinline__ uint32_t smem_u32(const void* p) {
    uint32_t a;
    asm("{ .reg .u64 t; cvta.to.shared.u64 t, %1; cvt.u32.u64 %0, t; }" : "=r"(a) : "l"(p));
    return a;
}
__device__ __forceinline__ void cp16(uint32_t dst, const void* src) {
    asm volatile("cp.async.cg.shared.global [%0], [%1], 16;" :: "r"(dst), "l"(src) : "memory");
}
__device__ __forceinline__ void cp_commit() {
    asm volatile("cp.async.commit_group;" ::: "memory");
}
template<int N> __device__ __forceinline__ void cp_wait() {
    asm volatile("cp.async.wait_group %0;" :: "n"(N) : "memory");
}
__device__ __forceinline__ void mma_f16(float* c, const uint32_t* a, const uint32_t* b) {
    asm volatile(
        "mma.sync.aligned.m16n8k16.row.col.f32.f16.f16.f32 "
        "{%0,%1,%2,%3}, {%4,%5,%6,%7}, {%8,%9}, {%0,%1,%2,%3};"
        : "+f"(c[0]), "+f"(c[1]), "+f"(c[2]), "+f"(c[3])
        : "r"(a[0]), "r"(a[1]), "r"(a[2]), "r"(a[3]), "r"(b[0]), "r"(b[1]));
}
__device__ __forceinline__ void ldsm_x4(uint32_t* r, uint32_t addr) {
    asm volatile("ldmatrix.sync.aligned.m8n8.x4.shared.b16 {%0,%1,%2,%3}, [%4];"
                 : "=r"(r[0]), "=r"(r[1]), "=r"(r[2]), "=r"(r[3]) : "r"(addr));
}
__device__ __forceinline__ void ldsm_x4_t(uint32_t* r, uint32_t addr) {
    asm volatile("ldmatrix.sync.aligned.m8n8.x4.trans.shared.b16 {%0,%1,%2,%3}, [%4];"
                 : "=r"(r[0]), "=r"(r[1]), "=r"(r[2]), "=r"(r[3]) : "r"(addr));
}

__device__ __forceinline__ float fexp(float x) {  // accurate for x <= 0
    float t = x * 1.4426950408889634f;
    float r = rintf(t), f = t - r;
    int i = (int)r;
    float p = 0.0013333558f;
    p = fmaf(p, f, 0.0096181291f);
    p = fmaf(p, f, 0.0555041087f);
    p = fmaf(p, f, 0.2402264476f);
    p = fmaf(p, f, 0.6931471806f);
    p = fmaf(p, f, 1.0f);
    float s = __int_as_float((i + 127) << 23);
    return (x < -80.f) ? 0.f : p * s;
}
__device__ __forceinline__ float silu(float g) {
    float t = fexp(-fabsf(g));
    float s = (g >= 0.f) ? 1.f / (1.f + t) : t / (1.f + t);
    return g * s;
}

// ---------------- weight transpose fp32 -> fp16: out[C,R] ------------------
__global__ __launch_bounds__(256)
void transpose_wh(const float* __restrict__ in, __half* __restrict__ out, int R, int C) {
    __shared__ float tb[64][65];
    const int rb = blockIdx.y * 64, cb = blockIdx.x * 64;
    const int tr = threadIdx.x >> 4;
    const int c4 = (threadIdx.x & 15) * 4;
#pragma unroll
    for (int i = 0; i < 4; i++) {
        int r = tr + i * 16;
        float4 v = *(const float4*)&in[(size_t)(rb + r) * C + cb + c4];
        tb[r][c4 + 0] = v.x; tb[r][c4 + 1] = v.y;
        tb[r][c4 + 2] = v.z; tb[r][c4 + 3] = v.w;
    }
    __syncthreads();
#pragma unroll
    for (int i = 0; i < 4; i++) {
        int r = tr + i * 16;
        size_t o = (size_t)(cb + r) * R + rb + c4;
        *(__half2*)&out[o]     = __floats2half2_rn(tb[c4 + 0][r], tb[c4 + 1][r]);
        *(__half2*)&out[o + 2] = __floats2half2_rn(tb[c4 + 2][r], tb[c4 + 3][r]);
    }
}

// ---------------- rmsnorm (fp16 out) ---------------------------------------
__global__ __launch_bounds__(256)
void rmsnorm_h(const float* __restrict__ x, const float* __restrict__ w,
               __half* __restrict__ o) {
    const int row = blockIdx.x;
    const float* xr = x + (size_t)row * DIM;
    float s = 0.f;
    for (int j = threadIdx.x; j < DIM; j += 256) { float v = xr[j]; s += v * v; }
    __shared__ float red[256];
    red[threadIdx.x] = s;
    __syncthreads();
    for (int st = 128; st > 0; st >>= 1) {
        if (threadIdx.x < st) red[threadIdx.x] += red[threadIdx.x + st];
        __syncthreads();
    }
    const float inv = rsqrtf(red[0] * (1.0f / DIM) + EPSV);
    __half* orow = o + (size_t)row * DIM;
    for (int j = threadIdx.x; j < DIM; j += 256)
        orow[j] = __float2half_rn(xr[j] * inv * w[j]);
}

// ---------------- RoPE -----------------------------------------------------
__global__ void init_invf_kernel() { g_invf[threadIdx.x] = pow(10000.0, -(double)threadIdx.x / 64.0); }
__global__ void rope_table_kernel() {
    int s = blockIdx.x, d = threadIdx.x;
    double ang = (double)s * g_invf[d];
    const double twopi = 6.283185307179586476925287;
    double r = ang - twopi * floor(ang / twopi + 0.5);
    float rf = (float)r;
    g_cs[s * 64 + d] = make_float2(cosf(rf), sinf(rf));
}
__global__ void rope_apply_h(__half* __restrict__ qkv) {
    const int s = blockIdx.x, h = blockIdx.y, d = threadIdx.x;
    __half* base = qkv + (size_t)s * QKVN +
                   ((h < NH) ? h * HD : (NH * HD + (h - NH) * HD));
    float2 cs = g_cs[s * 64 + d];
    float x0 = __half2float(base[d]), x1 = __half2float(base[d + 64]);
    base[d]      = __float2half_rn(x0 * cs.x - x1 * cs.y);
    base[d + 64] = __float2half_rn(x1 * cs.x + x0 * cs.y);
}

// ---------------------------------------------------------------------------
// Flash attention: one CTA = (128 q-rows, 1 head). 8 warps x 16 q-rows.
// K/V tiles 64 seqk x 128 HD (fp16, 256B rows, XOR-16B-chunk swizzle),
// double-buffered cp.async. Online softmax in registers; V via ldmatrix.trans.
// smem: Q 32KB + 2x(K 16KB + V 16KB) = 96KB -> 2 CTA/SM.
// ---------------------------------------------------------------------------
constexpr int FL_SMEM = 32768 + 2 * 32768;   // 98304

__global__ __launch_bounds__(256, 2)
void flash_attn(const __half* __restrict__ qkv, __half* __restrict__ outh,
                float iscale) {
    const int qt = (int)(gridDim.x - 1 - blockIdx.x);   // heavy tiles first
    const int h  = blockIdx.y;
    const int row0 = qt * 128;
    const __half* Qg = qkv + h * HD;
    const __half* Kg = qkv + NH * HD + (h >> 2) * HD;
    const __half* Vg = qkv + NH * HD + NKV * HD + (h >> 2) * HD;

    extern __shared__ char smc[];
    const uint32_t smQ = smem_u32(smc);

    const int tid = threadIdx.x, wid = tid >> 5, lane = tid & 31;
    const int lr = lane >> 2, lc = lane & 3, l7 = lane & 7;
    const int wrow = wid * 16;

    // Q tile: 128 rows x 16 chunks(16B); chunk stored at (c ^ (r&7))
    for (int j = 0; j < 8; j++) {
        int idx = j * 256 + tid, r = idx >> 4, c = idx & 15;
        uint32_t sw = (uint32_t)((c ^ (r & 7)) * 16);
        cp16(smQ + (uint32_t)r * 256 + sw, Qg + (size_t)(row0 + r) * QKVN + c * 8);
    }
    cp_commit();

    auto stageKV = [&](int s, int kt) {
        const uint32_t kB = smQ + 32768u + (uint32_t)s * 32768u;
        const uint32_t vB = kB + 16384u;
        for (int j = 0; j < 4; j++) {
            int idx = j * 256 + tid, r = idx >> 4, c = idx & 15;
            uint32_t sw = (uint32_t)((c ^ (r & 7)) * 16);
            cp16(kB + (uint32_t)r * 256 + sw, Kg + (size_t)(kt * 64 + r) * QKVN + c * 8);
            cp16(vB + (uint32_t)r * 256 + sw, Vg + (size_t)(kt * 64 + r) * QKVN + c * 8);
        }
    };

    const int nkt = 2 * qt + 2;
    stageKV(0, 0);
    cp_commit();
    if (nkt > 1) { stageKV(1, 1); cp_commit(); }

    float Oacc[16][4];
#pragma unroll
    for (int nt = 0; nt < 16; nt++)
#pragma unroll
        for (int i = 0; i < 4; i++) Oacc[nt][i] = 0.f;
    float m0 = -1e30f, m1 = -1e30f, l0 = 0.f, l1 = 0.f;

    const int aRow = wrow + ((lane >> 3) & 1) * 8 + l7;
    const int aSel = (lane >> 4) & 1;
    const int bRowB = ((lane >> 4) & 1) * 8 + l7;
    const int bSel = (lane >> 3) & 1;
    const int grow0 = row0 + wrow + lr;
    const int vg = lane >> 3;                 // ldsm.trans lane group
    const int vsub = vg & 1, vnq = vg >> 1;

    for (int kt = 0; kt < nkt; kt++) {
        if (kt == nkt - 1) cp_wait<0>(); else cp_wait<1>();
        __syncthreads();
        const uint32_t kB = smQ + 32768u + (uint32_t)(kt & 1) * 32768u;
        const uint32_t vB = kB + 16384u;

        float S[8][4];
#pragma unroll
        for (int nt = 0; nt < 8; nt++)
#pragma unroll
            for (int i = 0; i < 4; i++) S[nt][i] = 0.f;

        // S = Q @ K^T  (stripe 16 x 64)
#pragma unroll
        for (int dc = 0; dc < 8; dc++) {
            uint32_t qf[4];
            ldsm_x4(qf, smQ + (uint32_t)aRow * 256 +
                        (uint32_t)(((dc * 2 + aSel) ^ l7) * 16));
#pragma unroll
            for (int np = 0; np < 4; np++) {
                uint32_t kf[4];
                ldsm_x4(kf, kB + (uint32_t)(np * 16 + bRowB) * 256 +
                            (uint32_t)(((dc * 2 + bSel) ^ l7) * 16));
                mma_f16(S[np * 2],     qf, kf);
                mma_f16(S[np * 2 + 1], qf, kf + 2);
            }
        }

        // scale + causal mask
        const bool diag = (kt >= 2 * qt);
#pragma unroll
        for (int nt = 0; nt < 8; nt++) {
            int c0 = kt * 64 + nt * 8 + lc * 2;
            S[nt][0] *= iscale; S[nt][1] *= iscale;
            S[nt][2] *= iscale; S[nt][3] *= iscale;
            if (diag) {
                if (c0     > grow0)     S[nt][0] = -1e30f;
                if (c0 + 1 > grow0)     S[nt][1] = -1e30f;
                if (c0     > grow0 + 8) S[nt][2] = -1e30f;
                if (c0 + 1 > grow0 + 8) S[nt][3] = -1e30f;
            }
        }

        // online softmax
        float r0 = -1e30f, r1 = -1e30f;
#pragma unroll
        for (int nt = 0; nt < 8; nt++) {
            r0 = fmaxf(r0, fmaxf(S[nt][0], S[nt][1]));
            r1 = fmaxf(r1, fmaxf(S[nt][2], S[nt][3]));
        }
        r0 = fmaxf(r0, __shfl_xor_sync(0xffffffff, r0, 1));
        r0 = fmaxf(r0, __shfl_xor_sync(0xffffffff, r0, 2));
        r1 = fmaxf(r1, __shfl_xor_sync(0xffffffff, r1, 1));
        r1 = fmaxf(r1, __shfl_xor_sync(0xffffffff, r1, 2));
        const float mn0 = fmaxf(m0, r0), mn1 = fmaxf(m1, r1);
        const float sc0 = fexp(m0 - mn0), sc1 = fexp(m1 - mn1);
        m0 = mn0; m1 = mn1;

        uint32_t (*Su)[4] = (uint32_t(*)[4])S;
        float sum0 = 0.f, sum1 = 0.f;
#pragma unroll
        for (int nt = 0; nt < 8; nt++) {
            float e0 = fexp(S[nt][0] - mn0), e1 = fexp(S[nt][1] - mn0);
            float e2 = fexp(S[nt][2] - mn1), e3 = fexp(S[nt][3] - mn1);
            sum0 += e0 + e1; sum1 += e2 + e3;
            __half2 p01 = __floats2half2_rn(e0, e1);
            __half2 p23 = __floats2half2_rn(e2, e3);
            Su[nt][0] = *(uint32_t*)&p01;
            Su[nt][1] = *(uint32_t*)&p23;
        }
        sum0 += __shfl_xor_sync(0xffffffff, sum0, 1);
        sum0 += __shfl_xor_sync(0xffffffff, sum0, 2);
        sum1 += __shfl_xor_sync(0xffffffff, sum1, 1);
        sum1 += __shfl_xor_sync(0xffffffff, sum1, 2);
        l0 = l0 * sc0 + sum0;
        l1 = l1 * sc1 + sum1;

#pragma unroll
        for (int nt = 0; nt < 16; nt++) {
            Oacc[nt][0] *= sc0; Oacc[nt][1] *= sc0;
            Oacc[nt][2] *= sc1; Oacc[nt][3] *= sc1;
        }

        // O += P @ V (V fragments via ldmatrix.trans)
#pragma unroll
        for (int kc = 0; kc < 4; kc++) {
            uint32_t aP[4] = { Su[2 * kc][0], Su[2 * kc][1],
                               Su[2 * kc + 1][0], Su[2 * kc + 1][1] };
            const int vrow = kc * 16 + vsub * 8 + l7;
#pragma unroll
            for (int np = 0; np < 8; np++) {
                uint32_t vf[4];
                ldsm_x4_t(vf, vB + (uint32_t)vrow * 256 +
                              (uint32_t)((((np * 2 + vnq)) ^ l7) * 16));
                mma_f16(Oacc[np * 2],     aP, vf);
                mma_f16(Oacc[np * 2 + 1], aP, vf + 2);
            }
        }

        __syncthreads();
        if (kt + 2 < nkt) { stageKV(kt & 1, kt + 2); cp_commit(); }
    }

    const float inv0 = 1.0f / l0, inv1 = 1.0f / l1;
#pragma unroll
    for (int nt = 0; nt < 16; nt++) {
        int col = h * HD + nt * 8 + lc * 2;
        *(__half2*)&outh[(size_t)grow0 * (NH * HD) + col] =
            __floats2half2_rn(Oacc[nt][0] * inv0, Oacc[nt][1] * inv0);
        *(__half2*)&outh[(size_t)(grow0 + 8) * (NH * HD) + col] =
            __floats2half2_rn(Oacc[nt][2] * inv1, Oacc[nt][3] * inv1);
    }
}

// ---------------------------------------------------------------------------
// fp16 mma.sync GEMM (NT), as R13.  EPI: 0 fp16 plain, 1 fp32 +Aux.
// ---------------------------------------------------------------------------
constexpr int TILEB = 128 * 128;
constexpr int STGB  = 2 * TILEB;
constexpr int NSTAGE = 3;
constexpr int GEMM_SMEM = NSTAGE * STGB;  // 98304 B

template<int EPI>
__global__ __launch_bounds__(256, 2)
void mma_gemm(const __half* __restrict__ A, const __half* __restrict__ B,
              void* __restrict__ Cv, const float* __restrict__ Aux,
              int K, int lda, int ldb, int ldc) {
    const int row0 = blockIdx.y * 128;
    const int col0 = blockIdx.x * 128;

    extern __shared__ char smc[];
    const uint32_t smBase = smem_u32(smc);

    const int tid = threadIdx.x;
    const int wid = tid >> 5, lane = tid & 31;
    const int lr = lane >> 2, lc = lane & 3, l7 = lane & 7;
    const int wm = (wid & 1) * 64;
    const int wn = (wid >> 1) * 32;

    const int nkt = K / 64;
    const int aRow = wm + ((lane >> 3) & 1) * 8 + l7;
    const int bRow = wn + ((lane >> 4) & 1) * 8 + l7;
    const int aSel = (lane >> 4) & 1;
    const int bSel = (lane >> 3) & 1;

    auto stage = [&](int s, int kt) {
        const uint32_t aB = smBase + (uint32_t)(s * STGB);
        const uint32_t bB = aB + (uint32_t)TILEB;
        const __half* Ap = A + (size_t)row0 * lda + kt * 64;
        const __half* Bp = B + (size_t)col0 * ldb + kt * 64;
#pragma unroll
        for (int j = 0; j < 4; j++) {
            int idx = j * 256 + tid, r = idx >> 3, c = idx & 7;
            uint32_t sw = (uint32_t)((c ^ (r & 7)) * 16);
            cp16(aB + (uint32_t)r * 128 + sw, Ap + (size_t)r * lda + c * 8);
            cp16(bB + (uint32_t)r * 128 + sw, Bp + (size_t)r * ldb + c * 8);
        }
    };

    float acc[4][4][4];
#pragma unroll
    for (int mt = 0; mt < 4; mt++)
#pragma unroll
        for (int nt = 0; nt < 4; nt++)
#pragma unroll
            for (int i = 0; i < 4; i++) acc[mt][nt][i] = 0.f;

    stage(0, 0);
    cp_commit();
    if (nkt > 1) { stage(1, 1); cp_commit(); }

    uint32_t af[2][4][4], bf[2][4][2];
    auto loadFrags = [&](int buf, int ks, uint32_t aB4, uint32_t bB4) {
        const uint32_t ca = (uint32_t)(((ks * 2 + aSel) ^ l7) * 16);
        const uint32_t cb = (uint32_t)(((ks * 2 + bSel) ^ l7) * 16);
#pragma unroll
        for (int mt = 0; mt < 4; mt++)
            ldsm_x4(af[buf][mt], aB4 + (uint32_t)(aRow + mt * 16) * 128 + ca);
#pragma unroll
        for (int ntp = 0; ntp < 2; ntp++) {
            uint32_t tmp[4];
            ldsm_x4(tmp, bB4 + (uint32_t)(bRow + ntp * 16) * 128 + cb);
            bf[buf][ntp * 2][0] = tmp[0]; bf[buf][ntp * 2][1] = tmp[1];
            bf[buf][ntp * 2 + 1][0] = tmp[2]; bf[buf][ntp * 2 + 1][1] = tmp[3];
        }
    };

    int s = 0;
    for (int kt = 0; kt < nkt; kt++) {
        if (kt == nkt - 1) cp_wait<0>(); else cp_wait<1>();
        __syncthreads();
        if (kt + 2 < nkt) {
            int s2 = s + 2; if (s2 >= NSTAGE) s2 -= NSTAGE;
            stage(s2, kt + 2);
            cp_commit();
        }
        const uint32_t aB4 = smBase + (uint32_t)(s * STGB);
        const uint32_t bB4 = aB4 + (uint32_t)TILEB;
        loadFrags(0, 0, aB4, bB4);
#pragma unroll
        for (int ks = 0; ks < 4; ks++) {
            if (ks < 3) loadFrags((ks + 1) & 1, ks + 1, aB4, bB4);
            const int cb = ks & 1;
#pragma unroll
            for (int mt = 0; mt < 4; mt++)
#pragma unroll
                for (int nt = 0; nt < 4; nt++)
                    mma_f16(acc[mt][nt], af[cb][mt], bf[cb][nt]);
        }
        if (++s >= NSTAGE) s -= NSTAGE;
    }

    __half* Ch = (__half*)Cv;
    float*  Cf = (float*)Cv;
#pragma unroll
    for (int mt = 0; mt < 4; mt++) {
        const int ra = row0 + wm + mt * 16 + lr;
        const int rb = ra + 8;
#pragma unroll
        for (int nt = 0; nt < 4; nt++) {
            const int c = col0 + wn + nt * 8 + lc * 2;
            float* a4 = acc[mt][nt];
            const size_t ia = (size_t)ra * ldc + c;
            const size_t ib = (size_t)rb * ldc + c;
            if (EPI == 0) {
                *(__half2*)&Ch[ia] = __floats2half2_rn(a4[0], a4[1]);
                *(__half2*)&Ch[ib] = __floats2half2_rn(a4[2], a4[3]);
            } else {
                float2 xa = *(const float2*)&Aux[ia], xb = *(const float2*)&Aux[ib];
                *(float2*)&Cf[ia] = make_float2(a4[0] + xa.x, a4[1] + xa.y);
                *(float2*)&Cf[ib] = make_float2(a4[2] + xb.x, a4[3] + xb.y);
            }
        }
    }
}

// ---------------------------------------------------------------------------
// Fused gate+up MLP (R13-proven)
// ---------------------------------------------------------------------------
__global__ __launch_bounds__(256, 2)
void mma_mlp(const __half* __restrict__ A, const __half* __restrict__ Bg,
             const __half* __restrict__ Bu, __half* __restrict__ C) {
    const int row0 = blockIdx.y * 128;
    const int ffc0 = blockIdx.x * 64;

    extern __shared__ char smc[];
    const uint32_t smBase = smem_u32(smc);

    const int tid = threadIdx.x;
    const int wid = tid >> 5, lane = tid & 31;
    const int lr = lane >> 2, lc = lane & 3, l7 = lane & 7;
    const int role = wid >> 2;
    const int w2 = wid & 3;
    const int wm = (w2 & 1) * 64;
    const int wn = (w2 >> 1) * 32;

    const int aRow = wm + ((lane >> 3) & 1) * 8 + l7;
    const int bRow = wn + ((lane >> 4) & 1) * 8 + l7;
    const int aSel = (lane >> 4) & 1;
    const int bSel = (lane >> 3) & 1;

    constexpr int nkt = DIM / 64;

    auto stage = [&](int s, int kt) {
        const uint32_t aB = smBase + (uint32_t)(s * STGB);
        const uint32_t gB = aB + 16384u;
        const uint32_t uB = aB + 24576u;
        const __half* Ap = A + (size_t)row0 * DIM + kt * 64;
        const __half* Gp = Bg + (size_t)ffc0 * DIM + kt * 64;
        const __half* Up = Bu + (size_t)ffc0 * DIM + kt * 64;
#pragma unroll
        for (int j = 0; j < 4; j++) {
            int idx = j * 256 + tid, r = idx >> 3, c = idx & 7;
            uint32_t sw = (uint32_t)((c ^ (r & 7)) * 16);
            cp16(aB + (uint32_t)r * 128 + sw, Ap + (size_t)r * DIM + c * 8);
        }
#pragma unroll
        for (int j = 0; j < 2; j++) {
            int idx = j * 256 + tid, r = idx >> 3, c = idx & 7;
            uint32_t sw = (uint32_t)((c ^ (r & 7)) * 16);
            cp16(gB + (uint32_t)r * 128 + sw, Gp + (size_t)r * DIM + c * 8);
            cp16(uB + (uint32_t)r * 128 + sw, Up + (size_t)r * DIM + c * 8);
        }
    };

    float acc[4][4][4];
#pragma unroll
    for (int mt = 0; mt < 4; mt++)
#pragma unroll
        for (int nt = 0; nt < 4; nt++)
#pragma unroll
            for (int i = 0; i < 4; i++) acc[mt][nt][i] = 0.f;

    stage(0, 0);
    cp_commit();
    stage(1, 1);
    cp_commit();

    uint32_t af[2][4][4], bf[2][4][2];
    const uint32_t bOff = 16384u + (role ? 8192u : 0u);

    auto loadFrags = [&](int buf, int ks, uint32_t aB4, uint32_t bB4) {
        const uint32_t ca = (uint32_t)(((ks * 2 + aSel) ^ l7) * 16);
        const uint32_t cb = (uint32_t)(((ks * 2 + bSel) ^ l7) * 16);
#pragma unroll
        for (int mt = 0; mt < 4; mt++)
            ldsm_x4(af[buf][mt], aB4 + (uint32_t)(aRow + mt * 16) * 128 + ca);
#pragma unroll
        for (int ntp = 0; ntp < 2; ntp++) {
            uint32_t tmp[4];
            ldsm_x4(tmp, bB4 + (uint32_t)(bRow + ntp * 16) * 128 + cb);
            bf[buf][ntp * 2][0] = tmp[0]; bf[buf][ntp * 2][1] = tmp[1];
            bf[buf][ntp * 2 + 1][0] = tmp[2]; bf[buf][ntp * 2 + 1][1] = tmp[3];
        }
    };

    int s = 0;
    for (int kt = 0; kt < nkt; kt++) {
        if (kt == nkt - 1) cp_wait<0>(); else cp_wait<1>();
        __syncthreads();
        if (kt + 2 < nkt) {
            int s2 = s + 2; if (s2 >= NSTAGE) s2 -= NSTAGE;
            stage(s2, kt + 2);
            cp_commit();
        }
        const uint32_t aB4 = smBase + (uint32_t)(s * STGB);
        const uint32_t bB4 = aB4 + bOff;
        loadFrags(0, 0, aB4, bB4);
#pragma unroll
        for (int ks = 0; ks < 4; ks++) {
            if (ks < 3) loadFrags((ks + 1) & 1, ks + 1, aB4, bB4);
            const int cb = ks & 1;
#pragma unroll
            for (int mt = 0; mt < 4; mt++)
#pragma unroll
                for (int nt = 0; nt < 4; nt++)
                    mma_f16(acc[mt][nt], af[cb][mt], bf[cb][nt]);
        }
        if (++s >= NSTAGE) s -= NSTAGE;
    }

    __syncthreads();
    float* gsm = (float*)smc;
    if (role == 0) {
#pragma unroll
        for (int mt = 0; mt < 4; mt++) {
            const int ra = wm + mt * 16 + lr, rb = ra + 8;
#pragma unroll
            for (int nt = 0; nt < 4; nt++) {
                const int cl = wn + nt * 8 + lc * 2;
                float* a4 = acc[mt][nt];
                gsm[ra * 66 + cl] = a4[0]; gsm[ra * 66 + cl + 1] = a4[1];
                gsm[rb * 66 + cl] = a4[2]; gsm[rb * 66 + cl + 1] = a4[3];
            }
        }
    }
    __syncthreads();
    if (role == 1) {
#pragma unroll
        for (int mt = 0; mt < 4; mt++) {
            const int ra = wm + mt * 16 + lr, rb = ra + 8;
#pragma unroll
            for (int nt = 0; nt < 4; nt++) {
                const int cl = wn + nt * 8 + lc * 2;
                float* a4 = acc[mt][nt];
                float g0 = gsm[ra * 66 + cl], g1 = gsm[ra * 66 + cl + 1];
                float g2 = gsm[rb * 66 + cl], g3 = gsm[rb * 66 + cl + 1];
                size_t ia = (size_t)(row0 + ra) * FF + ffc0 + cl;
                size_t ib = (size_t)(row0 + rb) * FF + ffc0 + cl;
                *(__half2*)&C[ia] = __floats2half2_rn(silu(g0) * a4[0], silu(g1) * a4[1]);
                *(__half2*)&C[ib] = __floats2half2_rn(silu(g2) * a4[2], silu(g3) * a4[3]);
            }
        }
    }
}

// ---------------------------------------------------------------------------
extern "C" void kernel_launch(void* const* d_in, const int* in_sizes, int n_in,
                              void* d_out, int out_size) {
    (void)in_sizes; (void)n_in; (void)out_size;
    const float* x   = (const float*)d_in[0];
    const float* ln1 = (const float*)d_in[2];
    const float* Wq  = (const float*)d_in[3];
    const float* Wk  = (const float*)d_in[4];
    const float* Wv  = (const float*)d_in[5];
    const float* Wo  = (const float*)d_in[6];
    const float* ln2 = (const float*)d_in[7];
    const float* Wg  = (const float*)d_in[8];
    const float* Wu  = (const float*)d_in[9];
    const float* Wd  = (const float*)d_in[10];
    float* out = (float*)d_out;

    __half *h1h, *qkvh, *ath, *h2h, *mmh;
    __half *Wqkvh, *WoTh, *WgTh, *WuTh, *WdTh;
    float *x2;
    cudaGetSymbolAddress((void**)&h1h, g_h1h);   cudaGetSymbolAddress((void**)&qkvh, g_qkvh);
    cudaGetSymbolAddress((void**)&ath, g_ath);   cudaGetSymbolAddress((void**)&x2, g_x2);
    cudaGetSymbolAddress((void**)&h2h, g_h2h);   cudaGetSymbolAddress((void**)&mmh, g_mmh);
    cudaGetSymbolAddress((void**)&Wqkvh, g_Wqkvh); cudaGetSymbolAddress((void**)&WoTh, g_WoTh);
    cudaGetSymbolAddress((void**)&WgTh, g_WgTh);   cudaGetSymbolAddress((void**)&WuTh, g_WuTh);
    cudaGetSymbolAddress((void**)&WdTh, g_WdTh);

    cudaFuncSetAttribute(mma_gemm<0>, cudaFuncAttributeMaxDynamicSharedMemorySize, GEMM_SMEM);
    cudaFuncSetAttribute(mma_gemm<1>, cudaFuncAttributeMaxDynamicSharedMemorySize, GEMM_SMEM);
    cudaFuncSetAttribute(mma_mlp, cudaFuncAttributeMaxDynamicSharedMemorySize, GEMM_SMEM);
    cudaFuncSetAttribute(flash_attn, cudaFuncAttributeMaxDynamicSharedMemorySize, FL_SMEM);

    const float iscale = 0.08838834764831843f;  // 1/sqrt(128)

    transpose_wh<<<dim3(DIM / 64, DIM / 64), 256>>>(Wq, Wqkvh, DIM, DIM);
    transpose_wh<<<dim3(512 / 64, DIM / 64), 256>>>(Wk, Wqkvh + (size_t)2048 * DIM, DIM, 512);
    transpose_wh<<<dim3(512 / 64, DIM / 64), 256>>>(Wv, Wqkvh + (size_t)2560 * DIM, DIM, 512);
    transpose_wh<<<dim3(DIM / 64, DIM / 64), 256>>>(Wo, WoTh, DIM, DIM);
    transpose_wh<<<dim3(FF / 64, DIM / 64), 256>>>(Wg, WgTh, DIM, FF);
    transpose_wh<<<dim3(FF / 64, DIM / 64), 256>>>(Wu, WuTh, DIM, FF);
    transpose_wh<<<dim3(DIM / 64, FF / 64), 256>>>(Wd, WdTh, FF, DIM);
    init_invf_kernel<<<1, 64>>>();
    rope_table_kernel<<<SEQ, 64>>>();

    rmsnorm_h<<<SEQ, 256>>>(x, ln1, h1h);

    // fused QKV projection: qkv[S][3072]
    mma_gemm<0><<<dim3(QKVN / 128, 16, 1), 256, GEMM_SMEM>>>(
        h1h, Wqkvh, qkvh, nullptr, DIM, DIM, DIM, QKVN);

    rope_apply_h<<<dim3(SEQ, NH + NKV), 64>>>(qkvh);

    // fused flash attention -> ath [S][NH*HD]
    flash_attn<<<dim3(16, NH), 256, FL_SMEM>>>(qkvh, ath, iscale);

    // x2 = at @ Wo + x (fp32)
    mma_gemm<1><<<dim3(16, 16, 1), 256, GEMM_SMEM>>>(
        ath, WoTh, x2, x, DIM, DIM, DIM, DIM);

    rmsnorm_h<<<SEQ, 256>>>(x2, ln2, h2h);

    // fused gate+up MLP
    mma_mlp<<<dim3(FF / 64, 16, 1), 256, GEMM_SMEM>>>(h2h, WgTh, WuTh, mmh);

    // out = mm @ Wd + x2 (fp32)
    mma_gemm<1><<<dim3(16, 16, 1), 256, GEMM_SMEM>>>(
        mmh, WdTh, out, x2, FF, FF, FF, DIM);
}